// round 13
// baseline (speedup 1.0000x reference)
#include <cuda_runtime.h>
#include <cuda_bf16.h>
#include <math.h>
#include <stdint.h>

#define D 256
#define E 512
#define NTOK (32 * 4096)      // 131072 tokens
#define TM 128                 // tokens per CTA
#define NCH 128                // codes per chunk
#define NNC (E / NCH)          // 4
#define NST 4                  // 4 K-stages of 64 (hi-only bf16)
#define GRID_MAIN (NTOK / TM)  // 1024
#define MAXFLAG 16384
#define MAX2 16384
#define GAP_COARSE 0.02f       // bf16-noise-safe flag threshold
#define GAP_FINE 1.5e-4f       // fp32->quantized-ref protection band

// dynamic smem layout (main kernel)
#define OFF_A 0                          // 128 rows x 512B (bf16 hi, swizzled)
#define OFF_B 65536                      // 2 x 16384 stage buffers
#define OFF_C1 98304                     // u64[128]
#define OFF_C2 99328
#define OFF_G1 100352
#define OFF_G2 101376
#define OFF_WRED 102400                  // float[16]
#define SMEM_TOTAL (102400 + 64)

__device__ float g_en[E * D];            // fast-path normalized codebook (fp32)
__device__ float g_et[E * D];            // reference-emulated codebook
__device__ float g_se[E];                // emulated fp32 sum(et^2)
__device__ __nv_bfloat16 g_bhi[E * D];   // bf16 of g_en
__device__ float g_partial[GRID_MAIN];
__device__ int g_cnt;                    // tier-1 flagged count
__device__ int g_list[MAXFLAG];
__device__ int g_cnt2;                   // tier-3 flagged count
__device__ int4 g_list2[MAX2];           // {tok, i1|i2<<16, i3|i4<<16, 0}

__device__ __forceinline__ uint32_t smem_u32(const void* p) {
    uint32_t a;
    asm("{ .reg .u64 t; cvta.to.shared.u64 t, %1; cvt.u32.u64 %0, t; }" : "=r"(a) : "l"(p));
    return a;
}
// pack (orderable score << 32) | (~e): atomicMax -> max score, ties -> lowest e
__device__ __forceinline__ unsigned long long packkey(float v, unsigned e) {
    unsigned u = __float_as_uint(v);
    u = (u & 0x80000000u) ? ~u : (u | 0x80000000u);
    return ((unsigned long long)u << 32) | (unsigned long long)(0xFFFFFFFFu - e);
}
__device__ __forceinline__ float unpackscore(unsigned long long k) {
    unsigned u = (unsigned)(k >> 32);
    u = (u & 0x80000000u) ? (u & 0x7FFFFFFFu) : ~u;
    return __uint_as_float(u);
}
__device__ __forceinline__ unsigned unpackind(unsigned long long k) {
    return 0xFFFFFFFFu - (unsigned)k;
}

#define LDSM_X4(r0, r1, r2, r3, a) \
    asm volatile("ldmatrix.sync.aligned.m8n8.x4.shared.b16 {%0,%1,%2,%3}, [%4];" \
                 : "=r"(r0), "=r"(r1), "=r"(r2), "=r"(r3) : "r"(a))
#define LDSM_X2(r0, r1, a) \
    asm volatile("ldmatrix.sync.aligned.m8n8.x2.shared.b16 {%0,%1}, [%2];" \
                 : "=r"(r0), "=r"(r1) : "r"(a))
#define MMA16816(c, a0, a1, a2, a3, b0, b1) \
    asm volatile("mma.sync.aligned.m16n8k16.row.col.f32.bf16.bf16.f32 " \
                 "{%0,%1,%2,%3}, {%4,%5,%6,%7}, {%8,%9}, {%0,%1,%2,%3};" \
                 : "+f"((c)[0]), "+f"((c)[1]), "+f"((c)[2]), "+f"((c)[3]) \
                 : "r"(a0), "r"(a1), "r"(a2), "r"(a3), "r"(b0), "r"(b1))

// ---------------------------------------------------------------------------
// Kernel 1: normalize -> g_en, g_bhi, g_et/g_se. One warp per row.
// ---------------------------------------------------------------------------
__global__ __launch_bounds__(256) void normalize_kernel(const float* __restrict__ emb) {
    if (blockIdx.x == 0 && threadIdx.x == 0) { g_cnt = 0; g_cnt2 = 0; }
    int wid = threadIdx.x >> 5, lane = threadIdx.x & 31;
    int r = blockIdx.x * 8 + wid;
    const float4* row = (const float4*)(emb + (size_t)r * D);
    float4 v0 = row[lane];
    float4 v1 = row[lane + 32];

    float ss = v0.x * v0.x + v0.y * v0.y + v0.z * v0.z + v0.w * v0.w
             + v1.x * v1.x + v1.y * v1.y + v1.z * v1.z + v1.w * v1.w;
    double dss = (double)v0.x * v0.x + (double)v0.y * v0.y + (double)v0.z * v0.z
               + (double)v0.w * v0.w + (double)v1.x * v1.x + (double)v1.y * v1.y
               + (double)v1.z * v1.z + (double)v1.w * v1.w;
#pragma unroll
    for (int o = 16; o; o >>= 1) {
        ss += __shfl_xor_sync(0xFFFFFFFFu, ss, o);
        dss += __shfl_xor_sync(0xFFFFFFFFu, dss, o);
    }
    float inv = 1.0f / sqrtf(ss);
    float n[8] = {v0.x * inv, v0.y * inv, v0.z * inv, v0.w * inv,
                  v1.x * inv, v1.y * inv, v1.z * inv, v1.w * inv};
    float4* dst = (float4*)(g_en + (size_t)r * D);
    dst[lane] = make_float4(n[0], n[1], n[2], n[3]);
    dst[lane + 32] = make_float4(n[4], n[5], n[6], n[7]);
#pragma unroll
    for (int i = 0; i < 8; i++) {
        int c = (i < 4) ? (lane * 4 + i) : (128 + lane * 4 + i - 4);
        g_bhi[(size_t)r * D + c] = __float2bfloat16(n[i]);
    }

    // emulated path: norm = fl32(sqrt(fl32(sum))) ; et = fl32(emb / norm)
    float nf = sqrtf((float)dss);
    float e[8] = {v0.x / nf, v0.y / nf, v0.z / nf, v0.w / nf,
                  v1.x / nf, v1.y / nf, v1.z / nf, v1.w / nf};
    float4* dte = (float4*)(g_et + (size_t)r * D);
    dte[lane] = make_float4(e[0], e[1], e[2], e[3]);
    dte[lane + 32] = make_float4(e[4], e[5], e[6], e[7]);
    double se = 0.0;
#pragma unroll
    for (int i = 0; i < 8; i++) se += (double)e[i] * e[i];
#pragma unroll
    for (int o = 16; o; o >>= 1) se += __shfl_xor_sync(0xFFFFFFFFu, se, o);
    if (lane == 0) g_se[r] = (float)se;
}

// ---------------------------------------------------------------------------
// Kernel 2: bf16 hi-only HMMA GEMM, 512 threads / 16 warps (latency hiding),
// fused per-chunk top-2, gather epilogue; flags gap < GAP_COARSE to tier-2.
// ---------------------------------------------------------------------------
__global__ __launch_bounds__(512, 1) void main_kernel(const float* __restrict__ input,
                                                      float* __restrict__ out,
                                                      float* __restrict__ indf) {
    extern __shared__ char smem[];
    const uint32_t sb = smem_u32(smem);
    const int tid = threadIdx.x;
    const int wid = tid >> 5, lane = tid & 31;
    const int warp_m = wid >> 2;        // 0..3  (32 tokens each)
    const int warp_n = wid & 3;         // 0..3  (32 codes each)
    const int m0 = blockIdx.x * TM;

    unsigned long long* c1 = (unsigned long long*)(smem + OFF_C1);
    unsigned long long* c2 = (unsigned long long*)(smem + OFF_C2);
    unsigned long long* gb1 = (unsigned long long*)(smem + OFF_G1);
    unsigned long long* gb2 = (unsigned long long*)(smem + OFF_G2);
    float* wred = (float*)(smem + OFF_WRED);

    // ---- A fill: input fp32 -> smem bf16 hi, rows of 512B, swizzled ----
#pragma unroll
    for (int it = 0; it < 8; it++) {
        int task = tid + it * 512;          // 4096 tasks
        int m = task >> 5, g = task & 31;   // g = group of 8 dims
        const float* src = input + (size_t)(m0 + m) * D + g * 8;
        float4 f0 = *(const float4*)src;
        float4 f1 = *(const float4*)(src + 4);
        float xs[8] = {f0.x, f0.y, f0.z, f0.w, f1.x, f1.y, f1.z, f1.w};
        uint32_t hw[4];
#pragma unroll
        for (int i = 0; i < 4; i++) {
            __nv_bfloat16 h0 = __float2bfloat16(xs[2 * i]);
            __nv_bfloat16 h1 = __float2bfloat16(xs[2 * i + 1]);
            hw[i] = (uint32_t)__bfloat16_as_ushort(h0) | ((uint32_t)__bfloat16_as_ushort(h1) << 16);
        }
        *(uint4*)(smem + OFF_A + m * 512 + ((g ^ (m & 7)) << 4)) = make_uint4(hw[0], hw[1], hw[2], hw[3]);
    }
    if (tid < TM) { gb1[tid] = 0ull; gb2[tid] = 0ull; c1[tid] = 0ull; c2[tid] = 0ull; }
    __syncthreads();

#pragma unroll 1
    for (int nc = 0; nc < NNC; nc++) {
        float acc[2][4][4];
#pragma unroll
        for (int mi = 0; mi < 2; mi++)
#pragma unroll
            for (int ni = 0; ni < 4; ni++)
#pragma unroll
                for (int c = 0; c < 4; c++) acc[mi][ni][c] = 0.0f;

        uint4 pv[2];
        // preload stage 0: cols [0,64)
        {
#pragma unroll
            for (int i = 0; i < 2; i++) {
                int task = tid + i * 512;
                int n = task >> 3, cc = task & 7;
                pv[i] = *(const uint4*)(g_bhi + (size_t)(nc * NCH + n) * D + cc * 8);
            }
#pragma unroll
            for (int i = 0; i < 2; i++) {
                int task = tid + i * 512;
                int n = task >> 3, cc = task & 7;
                *(uint4*)(smem + OFF_B + n * 128 + ((cc ^ (n & 7)) << 4)) = pv[i];
            }
        }
        __syncthreads();

#pragma unroll 1
        for (int s = 0; s < NST; s++) {
            int buf = s & 1;
            if (s + 1 < NST) {
                int col0 = (s + 1) * 64;
#pragma unroll
                for (int i = 0; i < 2; i++) {
                    int task = tid + i * 512;
                    int n = task >> 3, cc = task & 7;
                    pv[i] = *(const uint4*)(g_bhi + (size_t)(nc * NCH + n) * D + col0 + cc * 8);
                }
            }
            int abase = s * 8;   // A cch base (16B units)
#pragma unroll
            for (int kk = 0; kk < 4; kk++) {
                uint32_t bfr[4][2];
                int ll = lane & 15;
#pragma unroll
                for (int ni = 0; ni < 4; ni++) {
                    int nb = warp_n * 32 + ni * 8 + (ll & 7);
                    int cch = kk * 2 + (ll >> 3);
                    uint32_t baddr = sb + OFF_B + buf * 16384 + nb * 128 + ((cch ^ (nb & 7)) << 4);
                    LDSM_X2(bfr[ni][0], bfr[ni][1], baddr);
                }
#pragma unroll
                for (int mi = 0; mi < 2; mi++) {
                    int row = warp_m * 32 + mi * 16 + (lane & 7) + ((lane >> 3) & 1) * 8;
                    int cch = abase + kk * 2 + (lane >> 4);
                    uint32_t aaddr = sb + OFF_A + row * 512 + ((cch ^ (row & 7)) << 4);
                    uint32_t a0, a1, a2, a3;
                    LDSM_X4(a0, a1, a2, a3, aaddr);
#pragma unroll
                    for (int ni = 0; ni < 4; ni++)
                        MMA16816(acc[mi][ni], a0, a1, a2, a3, bfr[ni][0], bfr[ni][1]);
                }
            }
            if (s + 1 < NST) {
                int nbuf = (s + 1) & 1;
#pragma unroll
                for (int i = 0; i < 2; i++) {
                    int task = tid + i * 512;
                    int n = task >> 3, cc = task & 7;
                    *(uint4*)(smem + OFF_B + nbuf * 16384 + n * 128 + ((cc ^ (n & 7)) << 4)) = pv[i];
                }
            }
            __syncthreads();
        }

        // ---- per-chunk top-2: local -> quad shfl merge -> two-pass atomicMax ----
        unsigned long long pk1[4], pk2[4];
        int idx = 0;
#pragma unroll
        for (int mi = 0; mi < 2; mi++)
#pragma unroll
            for (int h = 0; h < 2; h++) {
                unsigned long long k1 = 0ull, k2 = 0ull;
#pragma unroll
                for (int ni = 0; ni < 4; ni++)
#pragma unroll
                    for (int p = 0; p < 2; p++) {
                        float v = acc[mi][ni][h * 2 + p];
                        unsigned col = (unsigned)(nc * NCH + warp_n * 32 + ni * 8 + (lane & 3) * 2 + p);
                        unsigned long long k = packkey(v, col);
                        if (k > k1) { k2 = k1; k1 = k; }
                        else if (k > k2) k2 = k;
                    }
#pragma unroll
                for (int o = 1; o <= 2; o <<= 1) {
                    unsigned long long o1 = __shfl_xor_sync(0xFFFFFFFFu, k1, o);
                    unsigned long long o2 = __shfl_xor_sync(0xFFFFFFFFu, k2, o);
                    if (o1 > k1) { k2 = (k1 > o2) ? k1 : o2; k1 = o1; }
                    else if (o1 > k2) k2 = o1;
                }
                int r = warp_m * 32 + mi * 16 + h * 8 + (lane >> 2);
                if ((lane & 3) == 0) atomicMax(&c1[r], k1);
                pk1[idx] = k1; pk2[idx] = k2; idx++;
            }
        __syncthreads();
        idx = 0;
#pragma unroll
        for (int mi = 0; mi < 2; mi++)
#pragma unroll
            for (int h = 0; h < 2; h++) {
                if ((lane & 3) == 0) {
                    int r = warp_m * 32 + mi * 16 + h * 8 + (lane >> 2);
                    unsigned long long win = c1[r];
                    unsigned long long loc = (pk1[idx] == win) ? pk2[idx] : pk1[idx];
                    atomicMax(&c2[r], loc);
                }
                idx++;
            }
        __syncthreads();
        if (tid < TM) {
            unsigned long long a = gb1[tid], b = gb2[tid];
            unsigned long long x1 = c1[tid], x2 = c2[tid];
            if (x1 > a) { gb1[tid] = x1; gb2[tid] = (a > x2) ? a : x2; }
            else { gb2[tid] = (b > x1) ? b : x1; }
            c1[tid] = 0ull; c2[tid] = 0ull;
        }
        __syncthreads();
    }

    // ---- flag coarse near-ties for tier-2 fp32 re-scoring ----
    if (tid < TM) {
        float s1 = unpackscore(gb1[tid]);
        float s2 = unpackscore(gb2[tid]);
        if (s1 - s2 < GAP_COARSE) {
            int pos = atomicAdd(&g_cnt, 1);
            if (pos < MAXFLAG) g_list[pos] = m0 + tid;
        }
    }

    // ---- gather epilogue: each warp owns 8 tokens ----
    float dsum = 0.0f;
#pragma unroll 1
    for (int t = 0; t < 8; t++) {
        int m = wid * 8 + t;
        int ind = (int)unpackind(gb1[m]);
        size_t tok = (size_t)(m0 + m);
        const float4* q4 = (const float4*)(g_en + (size_t)ind * D);
        const float4* x4 = (const float4*)(input + tok * D);
        float4* o4 = (float4*)(out + tok * D);
#pragma unroll
        for (int c = 0; c < 2; c++) {
            int dd = c * 32 + lane;
            float4 q = q4[dd];
            float4 x = x4[dd];
            o4[dd] = q;
            float d0 = q.x - x.x, d1 = q.y - x.y, d2 = q.z - x.z, d3 = q.w - x.w;
            dsum += d0 * d0 + d1 * d1 + d2 * d2 + d3 * d3;
        }
        if (lane == 0) indf[tok] = (float)ind;
    }
#pragma unroll
    for (int o = 16; o; o >>= 1) dsum += __shfl_xor_sync(0xFFFFFFFFu, dsum, o);
    if (lane == 0) wred[wid] = dsum;
    __syncthreads();
    if (tid == 0) {
        float s = 0.0f;
        for (int w = 0; w < 16; w++) s += wred[w];
        g_partial[blockIdx.x] = s;
    }
}

// ---------------------------------------------------------------------------
// Kernel 3 (tier 2): exact fp32 re-score of coarse-flagged tokens; extracts
// TOP-4 candidates per token. Near-ties (gap < GAP_FINE) go to tier-3 with
// their candidate set; otherwise writes out/indf directly.
// ---------------------------------------------------------------------------
__global__ __launch_bounds__(256) void mid_refine_kernel(const float* __restrict__ input,
                                                         float* __restrict__ out,
                                                         float* __restrict__ indf) {
    __shared__ float xT[D][8];
    __shared__ int stok[8], sind[8];
    __shared__ unsigned long long t1[8], t2[8], t3[8], t4[8];
    int tid = threadIdx.x;
    int cnt = g_cnt;
    if (cnt > MAXFLAG) cnt = MAXFLAG;

    for (int base = blockIdx.x * 8; base < cnt; base += gridDim.x * 8) {
        int nt = cnt - base;
        if (nt > 8) nt = 8;
        if (tid < 8) {
            stok[tid] = g_list[base + ((tid < nt) ? tid : 0)];
            t1[tid] = 0ull; t2[tid] = 0ull; t3[tid] = 0ull; t4[tid] = 0ull;
        }
        __syncthreads();
#pragma unroll
        for (int j = 0; j < 8; j++)
            xT[tid][j] = input[(size_t)stok[j] * D + tid];
        __syncthreads();

        float acc[2][8];
#pragma unroll
        for (int p = 0; p < 2; p++)
#pragma unroll
            for (int j = 0; j < 8; j++) acc[p][j] = 0.0f;

        const float4* rowA = (const float4*)(g_en + (size_t)tid * D);
        const float4* rowB = (const float4*)(g_en + (size_t)(tid + 256) * D);
#pragma unroll 4
        for (int d4 = 0; d4 < 64; d4++) {
            float4 ra = rowA[d4];
            float4 rb = rowB[d4];
#pragma unroll
            for (int i = 0; i < 4; i++) {
                float va = (&ra.x)[i];
                float vb = (&rb.x)[i];
                const float* xr = &xT[d4 * 4 + i][0];
                float4 x0 = *(const float4*)xr;
                float4 x1 = *(const float4*)(xr + 4);
                float xv[8] = {x0.x, x0.y, x0.z, x0.w, x1.x, x1.y, x1.z, x1.w};
#pragma unroll
                for (int j = 0; j < 8; j++) {
                    acc[0][j] = fmaf(va, xv[j], acc[0][j]);
                    acc[1][j] = fmaf(vb, xv[j], acc[1][j]);
                }
            }
        }
        // precompute keys
        unsigned long long key[2][8];
#pragma unroll
        for (int p = 0; p < 2; p++)
#pragma unroll
            for (int j = 0; j < 8; j++)
                key[p][j] = packkey(acc[p][j], (unsigned)(tid + p * 256));
        // 4-pass top-4 extraction
#pragma unroll
        for (int p = 0; p < 2; p++)
#pragma unroll
            for (int j = 0; j < 8; j++) atomicMax(&t1[j], key[p][j]);
        __syncthreads();
#pragma unroll
        for (int p = 0; p < 2; p++)
#pragma unroll
            for (int j = 0; j < 8; j++)
                if (key[p][j] != t1[j]) atomicMax(&t2[j], key[p][j]);
        __syncthreads();
#pragma unroll
        for (int p = 0; p < 2; p++)
#pragma unroll
            for (int j = 0; j < 8; j++)
                if (key[p][j] != t1[j] && key[p][j] != t2[j]) atomicMax(&t3[j], key[p][j]);
        __syncthreads();
#pragma unroll
        for (int p = 0; p < 2; p++)
#pragma unroll
            for (int j = 0; j < 8; j++)
                if (key[p][j] != t1[j] && key[p][j] != t2[j] && key[p][j] != t3[j])
                    atomicMax(&t4[j], key[p][j]);
        __syncthreads();
        if (tid < nt) {
            float s1 = unpackscore(t1[tid]);
            float s2 = unpackscore(t2[tid]);
            int i1 = (int)unpackind(t1[tid]);
            int tok = stok[tid];
            sind[tid] = i1;
            indf[tok] = (float)i1;
            if (s1 - s2 < GAP_FINE) {
                int pos = atomicAdd(&g_cnt2, 1);
                if (pos < MAX2) {
                    int i2 = (int)unpackind(t2[tid]);
                    int i3 = (int)unpackind(t3[tid]);
                    int i4 = (int)unpackind(t4[tid]);
                    g_list2[pos] = make_int4(tok, i1 | (i2 << 16), i3 | (i4 << 16), 0);
                }
            }
        }
        __syncthreads();
#pragma unroll 1
        for (int j = 0; j < 8; j++) {
            if (j < nt)
                out[(size_t)stok[j] * D + tid] = g_en[(size_t)sind[j] * D + tid];
        }
        __syncthreads();
    }
}

// ---------------------------------------------------------------------------
// Kernel 4 (tier 3): reference-EMULATING adjudication among top-4 candidates.
// One warp per flagged token; fp64 dots, final dist rounded to fp32
// (reproduces the ~3e-5 quantization grid), argmin with lowest-index tiebreak.
// ---------------------------------------------------------------------------
__global__ __launch_bounds__(256) void refine_kernel(const float* __restrict__ input,
                                                     float* __restrict__ out,
                                                     float* __restrict__ indf) {
    int wid = threadIdx.x >> 5, lane = threadIdx.x & 31;
    int cnt = g_cnt2;
    if (cnt > MAX2) cnt = MAX2;

    for (int li = blockIdx.x * 8 + wid; li < cnt; li += gridDim.x * 8) {
        int4 ent = g_list2[li];
        int tok = ent.x;
        int cand[4] = {ent.y & 0xFFFF, (ent.y >> 16) & 0xFFFF,
                       ent.z & 0xFFFF, (ent.z >> 16) & 0xFFFF};

        const float4* xr = (const float4*)(input + (size_t)tok * D) + lane * 2;
        float4 x0 = xr[0], x1 = xr[1];
        double sx = (double)x0.x * x0.x + (double)x0.y * x0.y + (double)x0.z * x0.z
                  + (double)x0.w * x0.w + (double)x1.x * x1.x + (double)x1.y * x1.y
                  + (double)x1.z * x1.z + (double)x1.w * x1.w;
#pragma unroll
        for (int o = 16; o; o >>= 1) sx += __shfl_xor_sync(0xFFFFFFFFu, sx, o);
        float sx_f = (float)sx;

        unsigned long long bestk = 0xFFFFFFFFFFFFFFFFull;
#pragma unroll
        for (int c = 0; c < 4; c++) {
            int e = cand[c];
            const float4* er = (const float4*)(g_et + (size_t)e * D) + lane * 2;
            float4 e0 = er[0], e1 = er[1];
            double dot = (double)x0.x * e0.x + (double)x0.y * e0.y + (double)x0.z * e0.z
                       + (double)x0.w * e0.w + (double)x1.x * e1.x + (double)x1.y * e1.y
                       + (double)x1.z * e1.z + (double)x1.w * e1.w;
#pragma unroll
            for (int o = 16; o; o >>= 1) dot += __shfl_xor_sync(0xFFFFFFFFu, dot, o);
            float dist_f = (float)((double)sx_f - 2.0 * dot + (double)g_se[e]);
            unsigned long long k =
                ((unsigned long long)__float_as_uint(dist_f) << 32) | (unsigned)e;
            if (k < bestk) bestk = k;
        }
        int ind = (int)(unsigned)bestk;
        if (lane == 0) indf[tok] = (float)ind;
        const float4* q = (const float4*)(g_en + (size_t)ind * D) + lane * 2;
        float4* o4 = (float4*)(out + (size_t)tok * D) + lane * 2;
        o4[0] = q[0];
        o4[1] = q[1];
    }
}

// ---------------------------------------------------------------------------
// Kernel 5: deterministic final loss (coalesced column sums, 1024 threads).
// entropy = 2*E*sum(en^2) - 2*||sum_i en_i||^2
// ---------------------------------------------------------------------------
__global__ __launch_bounds__(1024) void finalize_kernel(float* __restrict__ loss_out) {
    __shared__ float ps[4][256], pq[4][256];
    __shared__ double red[1024];
    int tid = threadIdx.x;
    int col = tid & 255, seg = tid >> 8;

    float s = 0.0f, q = 0.0f;
    const float* base = g_en + (size_t)seg * 128 * D + col;
#pragma unroll 4
    for (int r = 0; r < 128; r++) {
        float v = base[(size_t)r * D];
        s += v;
        q += v * v;
    }
    ps[seg][col] = s;
    pq[seg][col] = q;

    red[tid] = (double)g_partial[tid];
    __syncthreads();
    for (int o = 512; o; o >>= 1) { if (tid < o) red[tid] += red[tid + o]; __syncthreads(); }
    double diff_sum = red[0];
    __syncthreads();

    double vss = 0.0, vq = 0.0;
    if (tid < 256) {
        float S = ps[0][tid] + ps[1][tid] + ps[2][tid] + ps[3][tid];
        float Q = pq[0][tid] + pq[1][tid] + pq[2][tid] + pq[3][tid];
        vss = (double)S * (double)S;
        vq = (double)Q;
    }
    red[tid] = vss;
    __syncthreads();
    for (int o = 512; o; o >>= 1) { if (tid < o) red[tid] += red[tid + o]; __syncthreads(); }
    double ss2 = red[0];
    __syncthreads();

    red[tid] = vq;
    __syncthreads();
    for (int o = 512; o; o >>= 1) { if (tid < o) red[tid] += red[tid + o]; __syncthreads(); }
    double sumsq = red[0];

    if (tid == 0) {
        double entropy = 2.0 * (double)E * sumsq - 2.0 * ss2;
        double diff = diff_sum / ((double)NTOK * (double)D);
        loss_out[0] = (float)(diff - entropy / (512.0 * 512.0));
    }
}

// ---------------------------------------------------------------------------
extern "C" void kernel_launch(void* const* d_in, const int* in_sizes, int n_in,
                              void* d_out, int out_size) {
    const float* input = (const float*)d_in[0];
    const float* emb = (const float*)d_in[1];
    if (n_in >= 2 && in_sizes[0] == E * D && in_sizes[1] == NTOK * D) {
        input = (const float*)d_in[1];
        emb = (const float*)d_in[0];
    }
    float* out = (float*)d_out;                      // [NTOK*D] quantized output
    float* loss = out + (size_t)NTOK * D;            // [1]      scalar loss
    float* indf = loss + 1;                          // [NTOK]   indices (as float)

    cudaFuncSetAttribute(main_kernel, cudaFuncAttributeMaxDynamicSharedMemorySize,
                         SMEM_TOTAL);

    normalize_kernel<<<E / 8, 256>>>(emb);
    main_kernel<<<GRID_MAIN, 512, SMEM_TOTAL>>>(input, out, indf);
    mid_refine_kernel<<<512, 256>>>(input, out, indf);
    refine_kernel<<<256, 256>>>(input, out, indf);
    finalize_kernel<<<1, 1024>>>(loss);
}

// round 14
// speedup vs baseline: 1.4155x; 1.4155x over previous
#include <cuda_runtime.h>
#include <cuda_bf16.h>
#include <math.h>
#include <stdint.h>

#define D 256
#define E 512
#define NTOK (32 * 4096)      // 131072 tokens
#define TM 128                 // tokens per CTA
#define NCH 128                // codes per chunk
#define NNC (E / NCH)          // 4
#define NST 4                  // 4 K-stages of 64 (hi-only bf16)
#define GRID_MAIN (NTOK / TM)  // 1024
#define MAXFLAG 16384
#define MAX2 16384
#define GAP_COARSE 0.02f       // bf16-noise-safe flag threshold
#define GAP_FINE 1.5e-4f       // fp32->quantized-ref protection band

// dynamic smem layout (main kernel)
#define OFF_A 0                          // 128 rows x 512B (bf16 hi, swizzled)
#define OFF_B 65536                      // 2 x 16384 stage buffers
#define OFF_C1 98304                     // u64[128]
#define OFF_C2 99328
#define OFF_G1 100352
#define OFF_G2 101376
#define OFF_WRED 102400                  // float[8]
#define SMEM_TOTAL (102400 + 64)

__device__ float g_en[E * D];            // fast-path normalized codebook (fp32)
__device__ float g_et[E * D];            // reference-emulated codebook
__device__ float g_se[E];                // emulated fp32 sum(et^2)
__device__ __nv_bfloat16 g_bhi[E * D];   // bf16 of g_en
__device__ float g_partial[GRID_MAIN];
__device__ int g_cnt;                    // tier-1 flagged count
__device__ int g_list[MAXFLAG];
__device__ int g_cnt2;                   // tier-3 flagged count
__device__ int4 g_list2[MAX2];           // {tok, i1|i2<<16, i3|i4<<16, 0}

__device__ __forceinline__ uint32_t smem_u32(const void* p) {
    uint32_t a;
    asm("{ .reg .u64 t; cvta.to.shared.u64 t, %1; cvt.u32.u64 %0, t; }" : "=r"(a) : "l"(p));
    return a;
}
// pack (orderable score << 32) | (~e): atomicMax -> max score, ties -> lowest e
__device__ __forceinline__ unsigned long long packkey(float v, unsigned e) {
    unsigned u = __float_as_uint(v);
    u = (u & 0x80000000u) ? ~u : (u | 0x80000000u);
    return ((unsigned long long)u << 32) | (unsigned long long)(0xFFFFFFFFu - e);
}
__device__ __forceinline__ float unpackscore(unsigned long long k) {
    unsigned u = (unsigned)(k >> 32);
    u = (u & 0x80000000u) ? (u & 0x7FFFFFFFu) : ~u;
    return __uint_as_float(u);
}
__device__ __forceinline__ unsigned unpackind(unsigned long long k) {
    return 0xFFFFFFFFu - (unsigned)k;
}

#define LDSM_X4(r0, r1, r2, r3, a) \
    asm volatile("ldmatrix.sync.aligned.m8n8.x4.shared.b16 {%0,%1,%2,%3}, [%4];" \
                 : "=r"(r0), "=r"(r1), "=r"(r2), "=r"(r3) : "r"(a))
#define LDSM_X2(r0, r1, a) \
    asm volatile("ldmatrix.sync.aligned.m8n8.x2.shared.b16 {%0,%1}, [%2];" \
                 : "=r"(r0), "=r"(r1) : "r"(a))
#define MMA16816(c, a0, a1, a2, a3, b0, b1) \
    asm volatile("mma.sync.aligned.m16n8k16.row.col.f32.bf16.bf16.f32 " \
                 "{%0,%1,%2,%3}, {%4,%5,%6,%7}, {%8,%9}, {%0,%1,%2,%3};" \
                 : "+f"((c)[0]), "+f"((c)[1]), "+f"((c)[2]), "+f"((c)[3]) \
                 : "r"(a0), "r"(a1), "r"(a2), "r"(a3), "r"(b0), "r"(b1))

// ---------------------------------------------------------------------------
// Kernel 1: normalize -> g_en, g_bhi, g_et/g_se. One warp per row.
// ---------------------------------------------------------------------------
__global__ __launch_bounds__(256) void normalize_kernel(const float* __restrict__ emb) {
    if (blockIdx.x == 0 && threadIdx.x == 0) { g_cnt = 0; g_cnt2 = 0; }
    int wid = threadIdx.x >> 5, lane = threadIdx.x & 31;
    int r = blockIdx.x * 8 + wid;
    const float4* row = (const float4*)(emb + (size_t)r * D);
    float4 v0 = row[lane];
    float4 v1 = row[lane + 32];

    float ss = v0.x * v0.x + v0.y * v0.y + v0.z * v0.z + v0.w * v0.w
             + v1.x * v1.x + v1.y * v1.y + v1.z * v1.z + v1.w * v1.w;
    double dss = (double)v0.x * v0.x + (double)v0.y * v0.y + (double)v0.z * v0.z
               + (double)v0.w * v0.w + (double)v1.x * v1.x + (double)v1.y * v1.y
               + (double)v1.z * v1.z + (double)v1.w * v1.w;
#pragma unroll
    for (int o = 16; o; o >>= 1) {
        ss += __shfl_xor_sync(0xFFFFFFFFu, ss, o);
        dss += __shfl_xor_sync(0xFFFFFFFFu, dss, o);
    }
    float inv = 1.0f / sqrtf(ss);
    float n[8] = {v0.x * inv, v0.y * inv, v0.z * inv, v0.w * inv,
                  v1.x * inv, v1.y * inv, v1.z * inv, v1.w * inv};
    float4* dst = (float4*)(g_en + (size_t)r * D);
    dst[lane] = make_float4(n[0], n[1], n[2], n[3]);
    dst[lane + 32] = make_float4(n[4], n[5], n[6], n[7]);
#pragma unroll
    for (int i = 0; i < 8; i++) {
        int c = (i < 4) ? (lane * 4 + i) : (128 + lane * 4 + i - 4);
        g_bhi[(size_t)r * D + c] = __float2bfloat16(n[i]);
    }

    // emulated path: norm = fl32(sqrt(fl32(sum))) ; et = fl32(emb / norm)
    float nf = sqrtf((float)dss);
    float e[8] = {v0.x / nf, v0.y / nf, v0.z / nf, v0.w / nf,
                  v1.x / nf, v1.y / nf, v1.z / nf, v1.w / nf};
    float4* dte = (float4*)(g_et + (size_t)r * D);
    dte[lane] = make_float4(e[0], e[1], e[2], e[3]);
    dte[lane + 32] = make_float4(e[4], e[5], e[6], e[7]);
    double se = 0.0;
#pragma unroll
    for (int i = 0; i < 8; i++) se += (double)e[i] * e[i];
#pragma unroll
    for (int o = 16; o; o >>= 1) se += __shfl_xor_sync(0xFFFFFFFFu, se, o);
    if (lane == 0) g_se[r] = (float)se;
}

// ---------------------------------------------------------------------------
// Kernel 2: bf16 hi-only HMMA GEMM (256 threads — proven round-12 config),
// fused per-chunk top-2, gather epilogue; flags gap < GAP_COARSE to tier-2.
// ---------------------------------------------------------------------------
__global__ __launch_bounds__(256, 1) void main_kernel(const float* __restrict__ input,
                                                      float* __restrict__ out,
                                                      float* __restrict__ indf) {
    extern __shared__ char smem[];
    const uint32_t sb = smem_u32(smem);
    const int tid = threadIdx.x;
    const int wid = tid >> 5, lane = tid & 31;
    const int warp_m = wid >> 2;        // 0..1  (64 tokens)
    const int warp_n = wid & 3;         // 0..3  (32 codes)
    const int m0 = blockIdx.x * TM;

    unsigned long long* c1 = (unsigned long long*)(smem + OFF_C1);
    unsigned long long* c2 = (unsigned long long*)(smem + OFF_C2);
    unsigned long long* gb1 = (unsigned long long*)(smem + OFF_G1);
    unsigned long long* gb2 = (unsigned long long*)(smem + OFF_G2);
    float* wred = (float*)(smem + OFF_WRED);

    // ---- A fill: input fp32 -> smem bf16 hi, rows of 512B, swizzled ----
#pragma unroll
    for (int it = 0; it < 16; it++) {
        int task = tid + it * 256;          // 4096 tasks
        int m = task >> 5, g = task & 31;   // g = group of 8 dims
        const float* src = input + (size_t)(m0 + m) * D + g * 8;
        float4 f0 = *(const float4*)src;
        float4 f1 = *(const float4*)(src + 4);
        float xs[8] = {f0.x, f0.y, f0.z, f0.w, f1.x, f1.y, f1.z, f1.w};
        uint32_t hw[4];
#pragma unroll
        for (int i = 0; i < 4; i++) {
            __nv_bfloat16 h0 = __float2bfloat16(xs[2 * i]);
            __nv_bfloat16 h1 = __float2bfloat16(xs[2 * i + 1]);
            hw[i] = (uint32_t)__bfloat16_as_ushort(h0) | ((uint32_t)__bfloat16_as_ushort(h1) << 16);
        }
        *(uint4*)(smem + OFF_A + m * 512 + ((g ^ (m & 7)) << 4)) = make_uint4(hw[0], hw[1], hw[2], hw[3]);
    }
    if (tid < TM) { gb1[tid] = 0ull; gb2[tid] = 0ull; c1[tid] = 0ull; c2[tid] = 0ull; }
    __syncthreads();

#pragma unroll 1
    for (int nc = 0; nc < NNC; nc++) {
        float acc[4][4][4];
#pragma unroll
        for (int mi = 0; mi < 4; mi++)
#pragma unroll
            for (int ni = 0; ni < 4; ni++)
#pragma unroll
                for (int c = 0; c < 4; c++) acc[mi][ni][c] = 0.0f;

        uint4 pv[4];
        // preload stage 0: cols [0,64)
        {
#pragma unroll
            for (int i = 0; i < 4; i++) {
                int task = tid + i * 256;
                int n = task >> 3, cc = task & 7;
                pv[i] = *(const uint4*)(g_bhi + (size_t)(nc * NCH + n) * D + cc * 8);
            }
#pragma unroll
            for (int i = 0; i < 4; i++) {
                int task = tid + i * 256;
                int n = task >> 3, cc = task & 7;
                *(uint4*)(smem + OFF_B + n * 128 + ((cc ^ (n & 7)) << 4)) = pv[i];
            }
        }
        __syncthreads();

#pragma unroll 1
        for (int s = 0; s < NST; s++) {
            int buf = s & 1;
            if (s + 1 < NST) {
                int col0 = (s + 1) * 64;
#pragma unroll
                for (int i = 0; i < 4; i++) {
                    int task = tid + i * 256;
                    int n = task >> 3, cc = task & 7;
                    pv[i] = *(const uint4*)(g_bhi + (size_t)(nc * NCH + n) * D + col0 + cc * 8);
                }
            }
            int abase = s * 8;   // A cch base (16B units)
#pragma unroll
            for (int kk = 0; kk < 4; kk++) {
                uint32_t bfr[4][2];
                int ll = lane & 15;
#pragma unroll
                for (int ni = 0; ni < 4; ni++) {
                    int nb = warp_n * 32 + ni * 8 + (ll & 7);
                    int cch = kk * 2 + (ll >> 3);
                    uint32_t baddr = sb + OFF_B + buf * 16384 + nb * 128 + ((cch ^ (nb & 7)) << 4);
                    LDSM_X2(bfr[ni][0], bfr[ni][1], baddr);
                }
#pragma unroll
                for (int mi = 0; mi < 4; mi++) {
                    int row = warp_m * 64 + mi * 16 + (lane & 7) + ((lane >> 3) & 1) * 8;
                    int cch = abase + kk * 2 + (lane >> 4);
                    uint32_t aaddr = sb + OFF_A + row * 512 + ((cch ^ (row & 7)) << 4);
                    uint32_t a0, a1, a2, a3;
                    LDSM_X4(a0, a1, a2, a3, aaddr);
#pragma unroll
                    for (int ni = 0; ni < 4; ni++)
                        MMA16816(acc[mi][ni], a0, a1, a2, a3, bfr[ni][0], bfr[ni][1]);
                }
            }
            if (s + 1 < NST) {
                int nbuf = (s + 1) & 1;
#pragma unroll
                for (int i = 0; i < 4; i++) {
                    int task = tid + i * 256;
                    int n = task >> 3, cc = task & 7;
                    *(uint4*)(smem + OFF_B + nbuf * 16384 + n * 128 + ((cc ^ (n & 7)) << 4)) = pv[i];
                }
            }
            __syncthreads();
        }

        // ---- per-chunk top-2: local -> quad shfl merge -> two-pass atomicMax ----
        unsigned long long pk1[8], pk2[8];
        int idx = 0;
#pragma unroll
        for (int mi = 0; mi < 4; mi++)
#pragma unroll
            for (int h = 0; h < 2; h++) {
                unsigned long long k1 = 0ull, k2 = 0ull;
#pragma unroll
                for (int ni = 0; ni < 4; ni++)
#pragma unroll
                    for (int p = 0; p < 2; p++) {
                        float v = acc[mi][ni][h * 2 + p];
                        unsigned col = (unsigned)(nc * NCH + warp_n * 32 + ni * 8 + (lane & 3) * 2 + p);
                        unsigned long long k = packkey(v, col);
                        if (k > k1) { k2 = k1; k1 = k; }
                        else if (k > k2) k2 = k;
                    }
#pragma unroll
                for (int o = 1; o <= 2; o <<= 1) {
                    unsigned long long o1 = __shfl_xor_sync(0xFFFFFFFFu, k1, o);
                    unsigned long long o2 = __shfl_xor_sync(0xFFFFFFFFu, k2, o);
                    if (o1 > k1) { k2 = (k1 > o2) ? k1 : o2; k1 = o1; }
                    else if (o1 > k2) k2 = o1;
                }
                int r = warp_m * 64 + mi * 16 + h * 8 + (lane >> 2);
                if ((lane & 3) == 0) atomicMax(&c1[r], k1);
                pk1[idx] = k1; pk2[idx] = k2; idx++;
            }
        __syncthreads();
        idx = 0;
#pragma unroll
        for (int mi = 0; mi < 4; mi++)
#pragma unroll
            for (int h = 0; h < 2; h++) {
                if ((lane & 3) == 0) {
                    int r = warp_m * 64 + mi * 16 + h * 8 + (lane >> 2);
                    unsigned long long win = c1[r];
                    unsigned long long loc = (pk1[idx] == win) ? pk2[idx] : pk1[idx];
                    atomicMax(&c2[r], loc);
                }
                idx++;
            }
        __syncthreads();
        if (tid < TM) {
            unsigned long long a = gb1[tid], b = gb2[tid];
            unsigned long long x1 = c1[tid], x2 = c2[tid];
            if (x1 > a) { gb1[tid] = x1; gb2[tid] = (a > x2) ? a : x2; }
            else { gb2[tid] = (b > x1) ? b : x1; }
            c1[tid] = 0ull; c2[tid] = 0ull;
        }
        __syncthreads();
    }

    // ---- flag coarse near-ties for tier-2 fp32 re-scoring ----
    if (tid < TM) {
        float s1 = unpackscore(gb1[tid]);
        float s2 = unpackscore(gb2[tid]);
        if (s1 - s2 < GAP_COARSE) {
            int pos = atomicAdd(&g_cnt, 1);
            if (pos < MAXFLAG) g_list[pos] = m0 + tid;
        }
    }

    // ---- gather epilogue: each warp owns 16 tokens ----
    float dsum = 0.0f;
#pragma unroll 1
    for (int t = 0; t < 16; t++) {
        int m = wid * 16 + t;
        int ind = (int)unpackind(gb1[m]);
        size_t tok = (size_t)(m0 + m);
        const float4* q4 = (const float4*)(g_en + (size_t)ind * D);
        const float4* x4 = (const float4*)(input + tok * D);
        float4* o4 = (float4*)(out + tok * D);
#pragma unroll
        for (int c = 0; c < 2; c++) {
            int dd = c * 32 + lane;
            float4 q = q4[dd];
            float4 x = x4[dd];
            o4[dd] = q;
            float d0 = q.x - x.x, d1 = q.y - x.y, d2 = q.z - x.z, d3 = q.w - x.w;
            dsum += d0 * d0 + d1 * d1 + d2 * d2 + d3 * d3;
        }
        if (lane == 0) indf[tok] = (float)ind;
    }
#pragma unroll
    for (int o = 16; o; o >>= 1) dsum += __shfl_xor_sync(0xFFFFFFFFu, dsum, o);
    if (lane == 0) wred[wid] = dsum;
    __syncthreads();
    if (tid == 0) {
        float s = 0.0f;
        for (int w = 0; w < 8; w++) s += wred[w];
        g_partial[blockIdx.x] = s;
    }
}

// ---------------------------------------------------------------------------
// Kernel 3 (tier 2): exact fp32 re-score of coarse-flagged tokens; extracts
// TOP-4 candidates per token. Near-ties (gap < GAP_FINE) go to tier-3 with
// their candidate set; otherwise writes out/indf directly.
// ---------------------------------------------------------------------------
__global__ __launch_bounds__(256) void mid_refine_kernel(const float* __restrict__ input,
                                                         float* __restrict__ out,
                                                         float* __restrict__ indf) {
    __shared__ float xT[D][8];
    __shared__ int stok[8], sind[8];
    __shared__ unsigned long long t1[8], t2[8], t3[8], t4[8];
    int tid = threadIdx.x;
    int cnt = g_cnt;
    if (cnt > MAXFLAG) cnt = MAXFLAG;

    for (int base = blockIdx.x * 8; base < cnt; base += gridDim.x * 8) {
        int nt = cnt - base;
        if (nt > 8) nt = 8;
        if (tid < 8) {
            stok[tid] = g_list[base + ((tid < nt) ? tid : 0)];
            t1[tid] = 0ull; t2[tid] = 0ull; t3[tid] = 0ull; t4[tid] = 0ull;
        }
        __syncthreads();
#pragma unroll
        for (int j = 0; j < 8; j++)
            xT[tid][j] = input[(size_t)stok[j] * D + tid];
        __syncthreads();

        float acc[2][8];
#pragma unroll
        for (int p = 0; p < 2; p++)
#pragma unroll
            for (int j = 0; j < 8; j++) acc[p][j] = 0.0f;

        const float4* rowA = (const float4*)(g_en + (size_t)tid * D);
        const float4* rowB = (const float4*)(g_en + (size_t)(tid + 256) * D);
#pragma unroll 4
        for (int d4 = 0; d4 < 64; d4++) {
            float4 ra = rowA[d4];
            float4 rb = rowB[d4];
#pragma unroll
            for (int i = 0; i < 4; i++) {
                float va = (&ra.x)[i];
                float vb = (&rb.x)[i];
                const float* xr = &xT[d4 * 4 + i][0];
                float4 x0 = *(const float4*)xr;
                float4 x1 = *(const float4*)(xr + 4);
                float xv[8] = {x0.x, x0.y, x0.z, x0.w, x1.x, x1.y, x1.z, x1.w};
#pragma unroll
                for (int j = 0; j < 8; j++) {
                    acc[0][j] = fmaf(va, xv[j], acc[0][j]);
                    acc[1][j] = fmaf(vb, xv[j], acc[1][j]);
                }
            }
        }
        // precompute keys
        unsigned long long key[2][8];
#pragma unroll
        for (int p = 0; p < 2; p++)
#pragma unroll
            for (int j = 0; j < 8; j++)
                key[p][j] = packkey(acc[p][j], (unsigned)(tid + p * 256));
        // 4-pass top-4 extraction
#pragma unroll
        for (int p = 0; p < 2; p++)
#pragma unroll
            for (int j = 0; j < 8; j++) atomicMax(&t1[j], key[p][j]);
        __syncthreads();
#pragma unroll
        for (int p = 0; p < 2; p++)
#pragma unroll
            for (int j = 0; j < 8; j++)
                if (key[p][j] != t1[j]) atomicMax(&t2[j], key[p][j]);
        __syncthreads();
#pragma unroll
        for (int p = 0; p < 2; p++)
#pragma unroll
            for (int j = 0; j < 8; j++)
                if (key[p][j] != t1[j] && key[p][j] != t2[j]) atomicMax(&t3[j], key[p][j]);
        __syncthreads();
#pragma unroll
        for (int p = 0; p < 2; p++)
#pragma unroll
            for (int j = 0; j < 8; j++)
                if (key[p][j] != t1[j] && key[p][j] != t2[j] && key[p][j] != t3[j])
                    atomicMax(&t4[j], key[p][j]);
        __syncthreads();
        if (tid < nt) {
            float s1 = unpackscore(t1[tid]);
            float s2 = unpackscore(t2[tid]);
            int i1 = (int)unpackind(t1[tid]);
            int tok = stok[tid];
            sind[tid] = i1;
            indf[tok] = (float)i1;
            if (s1 - s2 < GAP_FINE) {
                int pos = atomicAdd(&g_cnt2, 1);
                if (pos < MAX2) {
                    int i2 = (int)unpackind(t2[tid]);
                    int i3 = (int)unpackind(t3[tid]);
                    int i4 = (int)unpackind(t4[tid]);
                    g_list2[pos] = make_int4(tok, i1 | (i2 << 16), i3 | (i4 << 16), 0);
                }
            }
        }
        __syncthreads();
#pragma unroll 1
        for (int j = 0; j < 8; j++) {
            if (j < nt)
                out[(size_t)stok[j] * D + tid] = g_en[(size_t)sind[j] * D + tid];
        }
        __syncthreads();
    }
}

// ---------------------------------------------------------------------------
// Kernel 4 (tier 3): reference-EMULATING adjudication among top-4 candidates.
// One warp per flagged token; fp64 dots, final dist rounded to fp32
// (reproduces the ~3e-5 quantization grid), argmin with lowest-index tiebreak.
// ---------------------------------------------------------------------------
__global__ __launch_bounds__(256) void refine_kernel(const float* __restrict__ input,
                                                     float* __restrict__ out,
                                                     float* __restrict__ indf) {
    int wid = threadIdx.x >> 5, lane = threadIdx.x & 31;
    int cnt = g_cnt2;
    if (cnt > MAX2) cnt = MAX2;

    for (int li = blockIdx.x * 8 + wid; li < cnt; li += gridDim.x * 8) {
        int4 ent = g_list2[li];
        int tok = ent.x;
        int cand[4] = {ent.y & 0xFFFF, (ent.y >> 16) & 0xFFFF,
                       ent.z & 0xFFFF, (ent.z >> 16) & 0xFFFF};

        const float4* xr = (const float4*)(input + (size_t)tok * D) + lane * 2;
        float4 x0 = xr[0], x1 = xr[1];
        double sx = (double)x0.x * x0.x + (double)x0.y * x0.y + (double)x0.z * x0.z
                  + (double)x0.w * x0.w + (double)x1.x * x1.x + (double)x1.y * x1.y
                  + (double)x1.z * x1.z + (double)x1.w * x1.w;
#pragma unroll
        for (int o = 16; o; o >>= 1) sx += __shfl_xor_sync(0xFFFFFFFFu, sx, o);
        float sx_f = (float)sx;

        unsigned long long bestk = 0xFFFFFFFFFFFFFFFFull;
#pragma unroll
        for (int c = 0; c < 4; c++) {
            int e = cand[c];
            const float4* er = (const float4*)(g_et + (size_t)e * D) + lane * 2;
            float4 e0 = er[0], e1 = er[1];
            double dot = (double)x0.x * e0.x + (double)x0.y * e0.y + (double)x0.z * e0.z
                       + (double)x0.w * e0.w + (double)x1.x * e1.x + (double)x1.y * e1.y
                       + (double)x1.z * e1.z + (double)x1.w * e1.w;
#pragma unroll
            for (int o = 16; o; o >>= 1) dot += __shfl_xor_sync(0xFFFFFFFFu, dot, o);
            float dist_f = (float)((double)sx_f - 2.0 * dot + (double)g_se[e]);
            unsigned long long k =
                ((unsigned long long)__float_as_uint(dist_f) << 32) | (unsigned)e;
            if (k < bestk) bestk = k;
        }
        int ind = (int)(unsigned)bestk;
        if (lane == 0) indf[tok] = (float)ind;
        const float4* q = (const float4*)(g_en + (size_t)ind * D) + lane * 2;
        float4* o4 = (float4*)(out + (size_t)tok * D) + lane * 2;
        o4[0] = q[0];
        o4[1] = q[1];
    }
}

// ---------------------------------------------------------------------------
// Kernel 5: deterministic final loss (coalesced column sums, 1024 threads).
// entropy = 2*E*sum(en^2) - 2*||sum_i en_i||^2
// ---------------------------------------------------------------------------
__global__ __launch_bounds__(1024) void finalize_kernel(float* __restrict__ loss_out) {
    __shared__ float ps[4][256], pq[4][256];
    __shared__ double red[1024];
    int tid = threadIdx.x;
    int col = tid & 255, seg = tid >> 8;

    float s = 0.0f, q = 0.0f;
    const float* base = g_en + (size_t)seg * 128 * D + col;
#pragma unroll 4
    for (int r = 0; r < 128; r++) {
        float v = base[(size_t)r * D];
        s += v;
        q += v * v;
    }
    ps[seg][col] = s;
    pq[seg][col] = q;

    red[tid] = (double)g_partial[tid];
    __syncthreads();
    for (int o = 512; o; o >>= 1) { if (tid < o) red[tid] += red[tid + o]; __syncthreads(); }
    double diff_sum = red[0];
    __syncthreads();

    double vss = 0.0, vq = 0.0;
    if (tid < 256) {
        float S = ps[0][tid] + ps[1][tid] + ps[2][tid] + ps[3][tid];
        float Q = pq[0][tid] + pq[1][tid] + pq[2][tid] + pq[3][tid];
        vss = (double)S * (double)S;
        vq = (double)Q;
    }
    red[tid] = vss;
    __syncthreads();
    for (int o = 512; o; o >>= 1) { if (tid < o) red[tid] += red[tid + o]; __syncthreads(); }
    double ss2 = red[0];
    __syncthreads();

    red[tid] = vq;
    __syncthreads();
    for (int o = 512; o; o >>= 1) { if (tid < o) red[tid] += red[tid + o]; __syncthreads(); }
    double sumsq = red[0];

    if (tid == 0) {
        double entropy = 2.0 * (double)E * sumsq - 2.0 * ss2;
        double diff = diff_sum / ((double)NTOK * (double)D);
        loss_out[0] = (float)(diff - entropy / (512.0 * 512.0));
    }
}

// ---------------------------------------------------------------------------
extern "C" void kernel_launch(void* const* d_in, const int* in_sizes, int n_in,
                              void* d_out, int out_size) {
    const float* input = (const float*)d_in[0];
    const float* emb = (const float*)d_in[1];
    if (n_in >= 2 && in_sizes[0] == E * D && in_sizes[1] == NTOK * D) {
        input = (const float*)d_in[1];
        emb = (const float*)d_in[0];
    }
    float* out = (float*)d_out;                      // [NTOK*D] quantized output
    float* loss = out + (size_t)NTOK * D;            // [1]      scalar loss
    float* indf = loss + 1;                          // [NTOK]   indices (as float)

    cudaFuncSetAttribute(main_kernel, cudaFuncAttributeMaxDynamicSharedMemorySize,
                         SMEM_TOTAL);

    normalize_kernel<<<E / 8, 256>>>(emb);
    main_kernel<<<GRID_MAIN, 256, SMEM_TOTAL>>>(input, out, indf);
    mid_refine_kernel<<<512, 256>>>(input, out, indf);
    refine_kernel<<<256, 256>>>(input, out, indf);
    finalize_kernel<<<1, 1024>>>(loss);
}

// round 15
// speedup vs baseline: 1.6160x; 1.1417x over previous
#include <cuda_runtime.h>
#include <cuda_bf16.h>
#include <math.h>
#include <stdint.h>

#define D 256
#define E 512
#define NTOK (32 * 4096)      // 131072 tokens
#define TM 128                 // tokens per CTA
#define NCH 128                // codes per chunk
#define NNC (E / NCH)          // 4
#define NST 4                  // 4 K-stages of 64 (hi-only bf16)
#define GRID_MAIN (NTOK / TM)  // 1024
#define MAXFLAG 16384
#define MAX2 16384
#define GAP_COARSE 0.02f       // bf16-noise-safe flag threshold
#define GAP_FINE 1.5e-4f       // fp32->quantized-ref protection band

// dynamic smem layout (main kernel)
#define OFF_A 0                          // 128 rows x 512B (bf16 hi, swizzled)
#define OFF_B 65536                      // 2 x 16384 stage buffers
#define OFF_C1 98304                     // u64[128]
#define OFF_C2 99328
#define OFF_G1 100352
#define OFF_G2 101376
#define OFF_WRED 102400                  // float[8]
#define SMEM_TOTAL (102400 + 64)

__device__ float g_en[E * D];            // fast-path normalized codebook (fp32)
__device__ float g_et[E * D];            // reference-emulated codebook
__device__ float g_se[E];                // emulated fp32 sum(et^2)
__device__ __nv_bfloat16 g_bhi[E * D];   // bf16 of g_en
__device__ float g_partial[GRID_MAIN];
__device__ int g_cnt;                    // tier-1 flagged count
__device__ int g_list[MAXFLAG];
__device__ int g_cnt2;                   // tier-3 flagged count
__device__ int4 g_list2[MAX2];           // {tok, i1|i2<<16, i3|i4<<16, 0}

__device__ __forceinline__ uint32_t smem_u32(const void* p) {
    uint32_t a;
    asm("{ .reg .u64 t; cvta.to.shared.u64 t, %1; cvt.u32.u64 %0, t; }" : "=r"(a) : "l"(p));
    return a;
}
// pack (orderable score << 32) | (~e): atomicMax -> max score, ties -> lowest e
__device__ __forceinline__ unsigned long long packkey(float v, unsigned e) {
    unsigned u = __float_as_uint(v);
    u = (u & 0x80000000u) ? ~u : (u | 0x80000000u);
    return ((unsigned long long)u << 32) | (unsigned long long)(0xFFFFFFFFu - e);
}
__device__ __forceinline__ float unpackscore(unsigned long long k) {
    unsigned u = (unsigned)(k >> 32);
    u = (u & 0x80000000u) ? (u & 0x7FFFFFFFu) : ~u;
    return __uint_as_float(u);
}
__device__ __forceinline__ unsigned unpackind(unsigned long long k) {
    return 0xFFFFFFFFu - (unsigned)k;
}

#define LDSM_X4(r0, r1, r2, r3, a) \
    asm volatile("ldmatrix.sync.aligned.m8n8.x4.shared.b16 {%0,%1,%2,%3}, [%4];" \
                 : "=r"(r0), "=r"(r1), "=r"(r2), "=r"(r3) : "r"(a))
#define LDSM_X2(r0, r1, a) \
    asm volatile("ldmatrix.sync.aligned.m8n8.x2.shared.b16 {%0,%1}, [%2];" \
                 : "=r"(r0), "=r"(r1) : "r"(a))
#define MMA16816(c, a0, a1, a2, a3, b0, b1) \
    asm volatile("mma.sync.aligned.m16n8k16.row.col.f32.bf16.bf16.f32 " \
                 "{%0,%1,%2,%3}, {%4,%5,%6,%7}, {%8,%9}, {%0,%1,%2,%3};" \
                 : "+f"((c)[0]), "+f"((c)[1]), "+f"((c)[2]), "+f"((c)[3]) \
                 : "r"(a0), "r"(a1), "r"(a2), "r"(a3), "r"(b0), "r"(b1))

// ---------------------------------------------------------------------------
// Kernel 1: normalize -> g_en, g_bhi, g_et/g_se. One warp per row.
// ---------------------------------------------------------------------------
__global__ __launch_bounds__(256) void normalize_kernel(const float* __restrict__ emb) {
    if (blockIdx.x == 0 && threadIdx.x == 0) { g_cnt = 0; g_cnt2 = 0; }
    int wid = threadIdx.x >> 5, lane = threadIdx.x & 31;
    int r = blockIdx.x * 8 + wid;
    const float4* row = (const float4*)(emb + (size_t)r * D);
    float4 v0 = row[lane];
    float4 v1 = row[lane + 32];

    float ss = v0.x * v0.x + v0.y * v0.y + v0.z * v0.z + v0.w * v0.w
             + v1.x * v1.x + v1.y * v1.y + v1.z * v1.z + v1.w * v1.w;
    double dss = (double)v0.x * v0.x + (double)v0.y * v0.y + (double)v0.z * v0.z
               + (double)v0.w * v0.w + (double)v1.x * v1.x + (double)v1.y * v1.y
               + (double)v1.z * v1.z + (double)v1.w * v1.w;
#pragma unroll
    for (int o = 16; o; o >>= 1) {
        ss += __shfl_xor_sync(0xFFFFFFFFu, ss, o);
        dss += __shfl_xor_sync(0xFFFFFFFFu, dss, o);
    }
    float inv = 1.0f / sqrtf(ss);
    float n[8] = {v0.x * inv, v0.y * inv, v0.z * inv, v0.w * inv,
                  v1.x * inv, v1.y * inv, v1.z * inv, v1.w * inv};
    float4* dst = (float4*)(g_en + (size_t)r * D);
    dst[lane] = make_float4(n[0], n[1], n[2], n[3]);
    dst[lane + 32] = make_float4(n[4], n[5], n[6], n[7]);
#pragma unroll
    for (int i = 0; i < 8; i++) {
        int c = (i < 4) ? (lane * 4 + i) : (128 + lane * 4 + i - 4);
        g_bhi[(size_t)r * D + c] = __float2bfloat16(n[i]);
    }

    // emulated path: norm = fl32(sqrt(fl32(sum))) ; et = fl32(emb / norm)
    float nf = sqrtf((float)dss);
    float e[8] = {v0.x / nf, v0.y / nf, v0.z / nf, v0.w / nf,
                  v1.x / nf, v1.y / nf, v1.z / nf, v1.w / nf};
    float4* dte = (float4*)(g_et + (size_t)r * D);
    dte[lane] = make_float4(e[0], e[1], e[2], e[3]);
    dte[lane + 32] = make_float4(e[4], e[5], e[6], e[7]);
    double se = 0.0;
#pragma unroll
    for (int i = 0; i < 8; i++) se += (double)e[i] * e[i];
#pragma unroll
    for (int o = 16; o; o >>= 1) se += __shfl_xor_sync(0xFFFFFFFFu, se, o);
    if (lane == 0) g_se[r] = (float)se;
}

// ---------------------------------------------------------------------------
// Kernel 2: bf16 hi-only HMMA GEMM (256 threads, 2 CTAs/SM for stall overlap),
// fused per-chunk top-2, gather epilogue; flags gap < GAP_COARSE to tier-2.
// ---------------------------------------------------------------------------
__global__ __launch_bounds__(256, 2) void main_kernel(const float* __restrict__ input,
                                                      float* __restrict__ out,
                                                      float* __restrict__ indf) {
    extern __shared__ char smem[];
    const uint32_t sb = smem_u32(smem);
    const int tid = threadIdx.x;
    const int wid = tid >> 5, lane = tid & 31;
    const int warp_m = wid >> 2;        // 0..1  (64 tokens)
    const int warp_n = wid & 3;         // 0..3  (32 codes)
    const int m0 = blockIdx.x * TM;

    unsigned long long* c1 = (unsigned long long*)(smem + OFF_C1);
    unsigned long long* c2 = (unsigned long long*)(smem + OFF_C2);
    unsigned long long* gb1 = (unsigned long long*)(smem + OFF_G1);
    unsigned long long* gb2 = (unsigned long long*)(smem + OFF_G2);
    float* wred = (float*)(smem + OFF_WRED);

    // ---- A fill: input fp32 -> smem bf16 hi, rows of 512B, swizzled ----
#pragma unroll
    for (int it = 0; it < 16; it++) {
        int task = tid + it * 256;          // 4096 tasks
        int m = task >> 5, g = task & 31;   // g = group of 8 dims
        const float* src = input + (size_t)(m0 + m) * D + g * 8;
        float4 f0 = *(const float4*)src;
        float4 f1 = *(const float4*)(src + 4);
        float xs[8] = {f0.x, f0.y, f0.z, f0.w, f1.x, f1.y, f1.z, f1.w};
        uint32_t hw[4];
#pragma unroll
        for (int i = 0; i < 4; i++) {
            __nv_bfloat16 h0 = __float2bfloat16(xs[2 * i]);
            __nv_bfloat16 h1 = __float2bfloat16(xs[2 * i + 1]);
            hw[i] = (uint32_t)__bfloat16_as_ushort(h0) | ((uint32_t)__bfloat16_as_ushort(h1) << 16);
        }
        *(uint4*)(smem + OFF_A + m * 512 + ((g ^ (m & 7)) << 4)) = make_uint4(hw[0], hw[1], hw[2], hw[3]);
    }
    if (tid < TM) { gb1[tid] = 0ull; gb2[tid] = 0ull; c1[tid] = 0ull; c2[tid] = 0ull; }
    __syncthreads();

#pragma unroll 1
    for (int nc = 0; nc < NNC; nc++) {
        float acc[4][4][4];
#pragma unroll
        for (int mi = 0; mi < 4; mi++)
#pragma unroll
            for (int ni = 0; ni < 4; ni++)
#pragma unroll
                for (int c = 0; c < 4; c++) acc[mi][ni][c] = 0.0f;

        uint4 pv[4];
        // preload stage 0: cols [0,64)
        {
#pragma unroll
            for (int i = 0; i < 4; i++) {
                int task = tid + i * 256;
                int n = task >> 3, cc = task & 7;
                pv[i] = *(const uint4*)(g_bhi + (size_t)(nc * NCH + n) * D + cc * 8);
            }
#pragma unroll
            for (int i = 0; i < 4; i++) {
                int task = tid + i * 256;
                int n = task >> 3, cc = task & 7;
                *(uint4*)(smem + OFF_B + n * 128 + ((cc ^ (n & 7)) << 4)) = pv[i];
            }
        }
        __syncthreads();

#pragma unroll 1
        for (int s = 0; s < NST; s++) {
            int buf = s & 1;
            if (s + 1 < NST) {
                int col0 = (s + 1) * 64;
#pragma unroll
                for (int i = 0; i < 4; i++) {
                    int task = tid + i * 256;
                    int n = task >> 3, cc = task & 7;
                    pv[i] = *(const uint4*)(g_bhi + (size_t)(nc * NCH + n) * D + col0 + cc * 8);
                }
            }
            int abase = s * 8;   // A cch base (16B units)
#pragma unroll
            for (int kk = 0; kk < 4; kk++) {
                uint32_t bfr[4][2];
                int ll = lane & 15;
#pragma unroll
                for (int ni = 0; ni < 4; ni++) {
                    int nb = warp_n * 32 + ni * 8 + (ll & 7);
                    int cch = kk * 2 + (ll >> 3);
                    uint32_t baddr = sb + OFF_B + buf * 16384 + nb * 128 + ((cch ^ (nb & 7)) << 4);
                    LDSM_X2(bfr[ni][0], bfr[ni][1], baddr);
                }
#pragma unroll
                for (int mi = 0; mi < 4; mi++) {
                    int row = warp_m * 64 + mi * 16 + (lane & 7) + ((lane >> 3) & 1) * 8;
                    int cch = abase + kk * 2 + (lane >> 4);
                    uint32_t aaddr = sb + OFF_A + row * 512 + ((cch ^ (row & 7)) << 4);
                    uint32_t a0, a1, a2, a3;
                    LDSM_X4(a0, a1, a2, a3, aaddr);
#pragma unroll
                    for (int ni = 0; ni < 4; ni++)
                        MMA16816(acc[mi][ni], a0, a1, a2, a3, bfr[ni][0], bfr[ni][1]);
                }
            }
            if (s + 1 < NST) {
                int nbuf = (s + 1) & 1;
#pragma unroll
                for (int i = 0; i < 4; i++) {
                    int task = tid + i * 256;
                    int n = task >> 3, cc = task & 7;
                    *(uint4*)(smem + OFF_B + nbuf * 16384 + n * 128 + ((cc ^ (n & 7)) << 4)) = pv[i];
                }
            }
            __syncthreads();
        }

        // ---- per-chunk top-2: local -> quad shfl merge -> two-pass atomicMax ----
        unsigned long long pk1[8], pk2[8];
        int idx = 0;
#pragma unroll
        for (int mi = 0; mi < 4; mi++)
#pragma unroll
            for (int h = 0; h < 2; h++) {
                unsigned long long k1 = 0ull, k2 = 0ull;
#pragma unroll
                for (int ni = 0; ni < 4; ni++)
#pragma unroll
                    for (int p = 0; p < 2; p++) {
                        float v = acc[mi][ni][h * 2 + p];
                        unsigned col = (unsigned)(nc * NCH + warp_n * 32 + ni * 8 + (lane & 3) * 2 + p);
                        unsigned long long k = packkey(v, col);
                        if (k > k1) { k2 = k1; k1 = k; }
                        else if (k > k2) k2 = k;
                    }
#pragma unroll
                for (int o = 1; o <= 2; o <<= 1) {
                    unsigned long long o1 = __shfl_xor_sync(0xFFFFFFFFu, k1, o);
                    unsigned long long o2 = __shfl_xor_sync(0xFFFFFFFFu, k2, o);
                    if (o1 > k1) { k2 = (k1 > o2) ? k1 : o2; k1 = o1; }
                    else if (o1 > k2) k2 = o1;
                }
                int r = warp_m * 64 + mi * 16 + h * 8 + (lane >> 2);
                if ((lane & 3) == 0) atomicMax(&c1[r], k1);
                pk1[idx] = k1; pk2[idx] = k2; idx++;
            }
        __syncthreads();
        idx = 0;
#pragma unroll
        for (int mi = 0; mi < 4; mi++)
#pragma unroll
            for (int h = 0; h < 2; h++) {
                if ((lane & 3) == 0) {
                    int r = warp_m * 64 + mi * 16 + h * 8 + (lane >> 2);
                    unsigned long long win = c1[r];
                    unsigned long long loc = (pk1[idx] == win) ? pk2[idx] : pk1[idx];
                    atomicMax(&c2[r], loc);
                }
                idx++;
            }
        __syncthreads();
        if (tid < TM) {
            unsigned long long a = gb1[tid], b = gb2[tid];
            unsigned long long x1 = c1[tid], x2 = c2[tid];
            if (x1 > a) { gb1[tid] = x1; gb2[tid] = (a > x2) ? a : x2; }
            else { gb2[tid] = (b > x1) ? b : x1; }
            c1[tid] = 0ull; c2[tid] = 0ull;
        }
        __syncthreads();
    }

    // ---- flag coarse near-ties for tier-2 fp32 re-scoring ----
    if (tid < TM) {
        float s1 = unpackscore(gb1[tid]);
        float s2 = unpackscore(gb2[tid]);
        if (s1 - s2 < GAP_COARSE) {
            int pos = atomicAdd(&g_cnt, 1);
            if (pos < MAXFLAG) g_list[pos] = m0 + tid;
        }
    }

    // ---- gather epilogue: each warp owns 16 tokens ----
    float dsum = 0.0f;
#pragma unroll 1
    for (int t = 0; t < 16; t++) {
        int m = wid * 16 + t;
        int ind = (int)unpackind(gb1[m]);
        size_t tok = (size_t)(m0 + m);
        const float4* q4 = (const float4*)(g_en + (size_t)ind * D);
        const float4* x4 = (const float4*)(input + tok * D);
        float4* o4 = (float4*)(out + tok * D);
#pragma unroll
        for (int c = 0; c < 2; c++) {
            int dd = c * 32 + lane;
            float4 q = q4[dd];
            float4 x = x4[dd];
            o4[dd] = q;
            float d0 = q.x - x.x, d1 = q.y - x.y, d2 = q.z - x.z, d3 = q.w - x.w;
            dsum += d0 * d0 + d1 * d1 + d2 * d2 + d3 * d3;
        }
        if (lane == 0) indf[tok] = (float)ind;
    }
#pragma unroll
    for (int o = 16; o; o >>= 1) dsum += __shfl_xor_sync(0xFFFFFFFFu, dsum, o);
    if (lane == 0) wred[wid] = dsum;
    __syncthreads();
    if (tid == 0) {
        float s = 0.0f;
        for (int w = 0; w < 8; w++) s += wred[w];
        g_partial[blockIdx.x] = s;
    }
}

// ---------------------------------------------------------------------------
// Kernel 3 (tier 2): exact fp32 re-score of coarse-flagged tokens; extracts
// TOP-4 candidates per token. Near-ties (gap < GAP_FINE) go to tier-3 with
// their candidate set; otherwise writes out/indf directly.
// ---------------------------------------------------------------------------
__global__ __launch_bounds__(256) void mid_refine_kernel(const float* __restrict__ input,
                                                         float* __restrict__ out,
                                                         float* __restrict__ indf) {
    __shared__ float xT[D][8];
    __shared__ int stok[8], sind[8];
    __shared__ unsigned long long t1[8], t2[8], t3[8], t4[8];
    int tid = threadIdx.x;
    int cnt = g_cnt;
    if (cnt > MAXFLAG) cnt = MAXFLAG;

    for (int base = blockIdx.x * 8; base < cnt; base += gridDim.x * 8) {
        int nt = cnt - base;
        if (nt > 8) nt = 8;
        if (tid < 8) {
            stok[tid] = g_list[base + ((tid < nt) ? tid : 0)];
            t1[tid] = 0ull; t2[tid] = 0ull; t3[tid] = 0ull; t4[tid] = 0ull;
        }
        __syncthreads();
#pragma unroll
        for (int j = 0; j < 8; j++)
            xT[tid][j] = input[(size_t)stok[j] * D + tid];
        __syncthreads();

        float acc[2][8];
#pragma unroll
        for (int p = 0; p < 2; p++)
#pragma unroll
            for (int j = 0; j < 8; j++) acc[p][j] = 0.0f;

        const float4* rowA = (const float4*)(g_en + (size_t)tid * D);
        const float4* rowB = (const float4*)(g_en + (size_t)(tid + 256) * D);
#pragma unroll 4
        for (int d4 = 0; d4 < 64; d4++) {
            float4 ra = rowA[d4];
            float4 rb = rowB[d4];
#pragma unroll
            for (int i = 0; i < 4; i++) {
                float va = (&ra.x)[i];
                float vb = (&rb.x)[i];
                const float* xr = &xT[d4 * 4 + i][0];
                float4 x0 = *(const float4*)xr;
                float4 x1 = *(const float4*)(xr + 4);
                float xv[8] = {x0.x, x0.y, x0.z, x0.w, x1.x, x1.y, x1.z, x1.w};
#pragma unroll
                for (int j = 0; j < 8; j++) {
                    acc[0][j] = fmaf(va, xv[j], acc[0][j]);
                    acc[1][j] = fmaf(vb, xv[j], acc[1][j]);
                }
            }
        }
        // precompute keys
        unsigned long long key[2][8];
#pragma unroll
        for (int p = 0; p < 2; p++)
#pragma unroll
            for (int j = 0; j < 8; j++)
                key[p][j] = packkey(acc[p][j], (unsigned)(tid + p * 256));
        // 4-pass top-4 extraction
#pragma unroll
        for (int p = 0; p < 2; p++)
#pragma unroll
            for (int j = 0; j < 8; j++) atomicMax(&t1[j], key[p][j]);
        __syncthreads();
#pragma unroll
        for (int p = 0; p < 2; p++)
#pragma unroll
            for (int j = 0; j < 8; j++)
                if (key[p][j] != t1[j]) atomicMax(&t2[j], key[p][j]);
        __syncthreads();
#pragma unroll
        for (int p = 0; p < 2; p++)
#pragma unroll
            for (int j = 0; j < 8; j++)
                if (key[p][j] != t1[j] && key[p][j] != t2[j]) atomicMax(&t3[j], key[p][j]);
        __syncthreads();
#pragma unroll
        for (int p = 0; p < 2; p++)
#pragma unroll
            for (int j = 0; j < 8; j++)
                if (key[p][j] != t1[j] && key[p][j] != t2[j] && key[p][j] != t3[j])
                    atomicMax(&t4[j], key[p][j]);
        __syncthreads();
        if (tid < nt) {
            float s1 = unpackscore(t1[tid]);
            float s2 = unpackscore(t2[tid]);
            int i1 = (int)unpackind(t1[tid]);
            int tok = stok[tid];
            sind[tid] = i1;
            indf[tok] = (float)i1;
            if (s1 - s2 < GAP_FINE) {
                int pos = atomicAdd(&g_cnt2, 1);
                if (pos < MAX2) {
                    int i2 = (int)unpackind(t2[tid]);
                    int i3 = (int)unpackind(t3[tid]);
                    int i4 = (int)unpackind(t4[tid]);
                    g_list2[pos] = make_int4(tok, i1 | (i2 << 16), i3 | (i4 << 16), 0);
                }
            }
        }
        __syncthreads();
#pragma unroll 1
        for (int j = 0; j < 8; j++) {
            if (j < nt)
                out[(size_t)stok[j] * D + tid] = g_en[(size_t)sind[j] * D + tid];
        }
        __syncthreads();
    }
}

// ---------------------------------------------------------------------------
// Kernel 4 (tier 3): reference-EMULATING adjudication among top-4 candidates.
// One warp per flagged token; fp64 dots, final dist rounded to fp32
// (reproduces the ~3e-5 quantization grid), argmin with lowest-index tiebreak.
// ---------------------------------------------------------------------------
__global__ __launch_bounds__(256) void refine_kernel(const float* __restrict__ input,
                                                     float* __restrict__ out,
                                                     float* __restrict__ indf) {
    int wid = threadIdx.x >> 5, lane = threadIdx.x & 31;
    int cnt = g_cnt2;
    if (cnt > MAX2) cnt = MAX2;

    for (int li = blockIdx.x * 8 + wid; li < cnt; li += gridDim.x * 8) {
        int4 ent = g_list2[li];
        int tok = ent.x;
        int cand[4] = {ent.y & 0xFFFF, (ent.y >> 16) & 0xFFFF,
                       ent.z & 0xFFFF, (ent.z >> 16) & 0xFFFF};

        const float4* xr = (const float4*)(input + (size_t)tok * D) + lane * 2;
        float4 x0 = xr[0], x1 = xr[1];
        double sx = (double)x0.x * x0.x + (double)x0.y * x0.y + (double)x0.z * x0.z
                  + (double)x0.w * x0.w + (double)x1.x * x1.x + (double)x1.y * x1.y
                  + (double)x1.z * x1.z + (double)x1.w * x1.w;
#pragma unroll
        for (int o = 16; o; o >>= 1) sx += __shfl_xor_sync(0xFFFFFFFFu, sx, o);
        float sx_f = (float)sx;

        unsigned long long bestk = 0xFFFFFFFFFFFFFFFFull;
#pragma unroll
        for (int c = 0; c < 4; c++) {
            int e = cand[c];
            const float4* er = (const float4*)(g_et + (size_t)e * D) + lane * 2;
            float4 e0 = er[0], e1 = er[1];
            double dot = (double)x0.x * e0.x + (double)x0.y * e0.y + (double)x0.z * e0.z
                       + (double)x0.w * e0.w + (double)x1.x * e1.x + (double)x1.y * e1.y
                       + (double)x1.z * e1.z + (double)x1.w * e1.w;
#pragma unroll
            for (int o = 16; o; o >>= 1) dot += __shfl_xor_sync(0xFFFFFFFFu, dot, o);
            float dist_f = (float)((double)sx_f - 2.0 * dot + (double)g_se[e]);
            unsigned long long k =
                ((unsigned long long)__float_as_uint(dist_f) << 32) | (unsigned)e;
            if (k < bestk) bestk = k;
        }
        int ind = (int)(unsigned)bestk;
        if (lane == 0) indf[tok] = (float)ind;
        const float4* q = (const float4*)(g_en + (size_t)ind * D) + lane * 2;
        float4* o4 = (float4*)(out + (size_t)tok * D) + lane * 2;
        o4[0] = q[0];
        o4[1] = q[1];
    }
}

// ---------------------------------------------------------------------------
// Kernel 5: deterministic final loss (coalesced column sums, 1024 threads).
// entropy = 2*E*sum(en^2) - 2*||sum_i en_i||^2
// ---------------------------------------------------------------------------
__global__ __launch_bounds__(1024) void finalize_kernel(float* __restrict__ loss_out) {
    __shared__ float ps[4][256], pq[4][256];
    __shared__ double red[1024];
    int tid = threadIdx.x;
    int col = tid & 255, seg = tid >> 8;

    float s = 0.0f, q = 0.0f;
    const float* base = g_en + (size_t)seg * 128 * D + col;
#pragma unroll 4
    for (int r = 0; r < 128; r++) {
        float v = base[(size_t)r * D];
        s += v;
        q += v * v;
    }
    ps[seg][col] = s;
    pq[seg][col] = q;

    red[tid] = (double)g_partial[tid];
    __syncthreads();
    for (int o = 512; o; o >>= 1) { if (tid < o) red[tid] += red[tid + o]; __syncthreads(); }
    double diff_sum = red[0];
    __syncthreads();

    double vss = 0.0, vq = 0.0;
    if (tid < 256) {
        float S = ps[0][tid] + ps[1][tid] + ps[2][tid] + ps[3][tid];
        float Q = pq[0][tid] + pq[1][tid] + pq[2][tid] + pq[3][tid];
        vss = (double)S * (double)S;
        vq = (double)Q;
    }
    red[tid] = vss;
    __syncthreads();
    for (int o = 512; o; o >>= 1) { if (tid < o) red[tid] += red[tid + o]; __syncthreads(); }
    double ss2 = red[0];
    __syncthreads();

    red[tid] = vq;
    __syncthreads();
    for (int o = 512; o; o >>= 1) { if (tid < o) red[tid] += red[tid + o]; __syncthreads(); }
    double sumsq = red[0];

    if (tid == 0) {
        double entropy = 2.0 * (double)E * sumsq - 2.0 * ss2;
        double diff = diff_sum / ((double)NTOK * (double)D);
        loss_out[0] = (float)(diff - entropy / (512.0 * 512.0));
    }
}

// ---------------------------------------------------------------------------
extern "C" void kernel_launch(void* const* d_in, const int* in_sizes, int n_in,
                              void* d_out, int out_size) {
    const float* input = (const float*)d_in[0];
    const float* emb = (const float*)d_in[1];
    if (n_in >= 2 && in_sizes[0] == E * D && in_sizes[1] == NTOK * D) {
        input = (const float*)d_in[1];
        emb = (const float*)d_in[0];
    }
    float* out = (float*)d_out;                      // [NTOK*D] quantized output
    float* loss = out + (size_t)NTOK * D;            // [1]      scalar loss
    float* indf = loss + 1;                          // [NTOK]   indices (as float)

    cudaFuncSetAttribute(main_kernel, cudaFuncAttributeMaxDynamicSharedMemorySize,
                         SMEM_TOTAL);

    normalize_kernel<<<E / 8, 256>>>(emb);
    main_kernel<<<GRID_MAIN, 256, SMEM_TOTAL>>>(input, out, indf);
    mid_refine_kernel<<<512, 256>>>(input, out, indf);
    refine_kernel<<<256, 256>>>(input, out, indf);
    finalize_kernel<<<1, 1024>>>(loss);
}

// round 16
// speedup vs baseline: 1.8691x; 1.1566x over previous
#include <cuda_runtime.h>
#include <cuda_bf16.h>
#include <math.h>
#include <stdint.h>

#define D 256
#define E 512
#define NTOK (32 * 4096)      // 131072 tokens
#define TM 128                 // tokens per CTA
#define NCH 128                // codes per chunk
#define NNC (E / NCH)          // 4
#define NST 4                  // 4 K-stages of 64 (hi-only bf16)
#define GRID_MAIN (NTOK / TM)  // 1024
#define MAXFLAG 32768
#define MAX2 16384
#define NT 16                  // tokens per mid-refine CTA iteration
#define GAP_COARSE 0.02f       // bf16-noise-safe flag threshold
#define GAP_FINE 1.5e-4f       // fp32->quantized-ref protection band

// dynamic smem layout (main kernel)
#define OFF_A 0                          // 128 rows x 512B (bf16 hi, swizzled)
#define OFF_B 65536                      // 2 x 16384 stage buffers
#define OFF_C1 98304                     // u64[128]
#define OFF_C2 99328
#define OFF_G1 100352
#define OFF_G2 101376
#define OFF_WRED 102400                  // float[8]
#define SMEM_TOTAL (102400 + 64)

__device__ float g_en[E * D];            // fast-path normalized codebook (fp32)
__device__ float g_et[E * D];            // reference-emulated codebook
__device__ float g_se[E];                // emulated fp32 sum(et^2)
__device__ __nv_bfloat16 g_bhi[E * D];   // bf16 of g_en
__device__ float g_partial[GRID_MAIN];
__device__ int g_cnt;                    // tier-1 flagged count
__device__ int g_list[MAXFLAG];
__device__ int g_cnt2;                   // tier-3 flagged count
__device__ int4 g_list2[MAX2];           // {tok, i1|i2<<16, i3|i4<<16, 0}
__device__ float g_fs[4][256];           // finalize partial col sums
__device__ float g_fq[4][256];           // finalize partial col sq-sums

__device__ __forceinline__ uint32_t smem_u32(const void* p) {
    uint32_t a;
    asm("{ .reg .u64 t; cvta.to.shared.u64 t, %1; cvt.u32.u64 %0, t; }" : "=r"(a) : "l"(p));
    return a;
}
// pack (orderable score << 32) | (~e): atomicMax -> max score, ties -> lowest e
__device__ __forceinline__ unsigned long long packkey(float v, unsigned e) {
    unsigned u = __float_as_uint(v);
    u = (u & 0x80000000u) ? ~u : (u | 0x80000000u);
    return ((unsigned long long)u << 32) | (unsigned long long)(0xFFFFFFFFu - e);
}
__device__ __forceinline__ float unpackscore(unsigned long long k) {
    unsigned u = (unsigned)(k >> 32);
    u = (u & 0x80000000u) ? (u & 0x7FFFFFFFu) : ~u;
    return __uint_as_float(u);
}
__device__ __forceinline__ unsigned unpackind(unsigned long long k) {
    return 0xFFFFFFFFu - (unsigned)k;
}

#define LDSM_X4(r0, r1, r2, r3, a) \
    asm volatile("ldmatrix.sync.aligned.m8n8.x4.shared.b16 {%0,%1,%2,%3}, [%4];" \
                 : "=r"(r0), "=r"(r1), "=r"(r2), "=r"(r3) : "r"(a))
#define LDSM_X2(r0, r1, a) \
    asm volatile("ldmatrix.sync.aligned.m8n8.x2.shared.b16 {%0,%1}, [%2];" \
                 : "=r"(r0), "=r"(r1) : "r"(a))
#define MMA16816(c, a0, a1, a2, a3, b0, b1) \
    asm volatile("mma.sync.aligned.m16n8k16.row.col.f32.bf16.bf16.f32 " \
                 "{%0,%1,%2,%3}, {%4,%5,%6,%7}, {%8,%9}, {%0,%1,%2,%3};" \
                 : "+f"((c)[0]), "+f"((c)[1]), "+f"((c)[2]), "+f"((c)[3]) \
                 : "r"(a0), "r"(a1), "r"(a2), "r"(a3), "r"(b0), "r"(b1))

// ---------------------------------------------------------------------------
// Kernel 1: normalize -> g_en, g_bhi, g_et/g_se. One warp per row.
// ---------------------------------------------------------------------------
__global__ __launch_bounds__(256) void normalize_kernel(const float* __restrict__ emb) {
    if (blockIdx.x == 0 && threadIdx.x == 0) { g_cnt = 0; g_cnt2 = 0; }
    int wid = threadIdx.x >> 5, lane = threadIdx.x & 31;
    int r = blockIdx.x * 8 + wid;
    const float4* row = (const float4*)(emb + (size_t)r * D);
    float4 v0 = row[lane];
    float4 v1 = row[lane + 32];

    float ss = v0.x * v0.x + v0.y * v0.y + v0.z * v0.z + v0.w * v0.w
             + v1.x * v1.x + v1.y * v1.y + v1.z * v1.z + v1.w * v1.w;
    double dss = (double)v0.x * v0.x + (double)v0.y * v0.y + (double)v0.z * v0.z
               + (double)v0.w * v0.w + (double)v1.x * v1.x + (double)v1.y * v1.y
               + (double)v1.z * v1.z + (double)v1.w * v1.w;
#pragma unroll
    for (int o = 16; o; o >>= 1) {
        ss += __shfl_xor_sync(0xFFFFFFFFu, ss, o);
        dss += __shfl_xor_sync(0xFFFFFFFFu, dss, o);
    }
    float inv = 1.0f / sqrtf(ss);
    float n[8] = {v0.x * inv, v0.y * inv, v0.z * inv, v0.w * inv,
                  v1.x * inv, v1.y * inv, v1.z * inv, v1.w * inv};
    float4* dst = (float4*)(g_en + (size_t)r * D);
    dst[lane] = make_float4(n[0], n[1], n[2], n[3]);
    dst[lane + 32] = make_float4(n[4], n[5], n[6], n[7]);
#pragma unroll
    for (int i = 0; i < 8; i++) {
        int c = (i < 4) ? (lane * 4 + i) : (128 + lane * 4 + i - 4);
        g_bhi[(size_t)r * D + c] = __float2bfloat16(n[i]);
    }

    // emulated path: norm = fl32(sqrt(fl32(sum))) ; et = fl32(emb / norm)
    float nf = sqrtf((float)dss);
    float e[8] = {v0.x / nf, v0.y / nf, v0.z / nf, v0.w / nf,
                  v1.x / nf, v1.y / nf, v1.z / nf, v1.w / nf};
    float4* dte = (float4*)(g_et + (size_t)r * D);
    dte[lane] = make_float4(e[0], e[1], e[2], e[3]);
    dte[lane + 32] = make_float4(e[4], e[5], e[6], e[7]);
    double se = 0.0;
#pragma unroll
    for (int i = 0; i < 8; i++) se += (double)e[i] * e[i];
#pragma unroll
    for (int o = 16; o; o >>= 1) se += __shfl_xor_sync(0xFFFFFFFFu, se, o);
    if (lane == 0) g_se[r] = (float)se;
}

// ---------------------------------------------------------------------------
// Kernel 2: bf16 hi-only HMMA GEMM (256 threads, 2 CTAs/SM — r15 proven),
// fused per-chunk top-2, gather epilogue; flags gap < GAP_COARSE to tier-2.
// ---------------------------------------------------------------------------
__global__ __launch_bounds__(256, 2) void main_kernel(const float* __restrict__ input,
                                                      float* __restrict__ out,
                                                      float* __restrict__ indf) {
    extern __shared__ char smem[];
    const uint32_t sb = smem_u32(smem);
    const int tid = threadIdx.x;
    const int wid = tid >> 5, lane = tid & 31;
    const int warp_m = wid >> 2;        // 0..1  (64 tokens)
    const int warp_n = wid & 3;         // 0..3  (32 codes)
    const int m0 = blockIdx.x * TM;

    unsigned long long* c1 = (unsigned long long*)(smem + OFF_C1);
    unsigned long long* c2 = (unsigned long long*)(smem + OFF_C2);
    unsigned long long* gb1 = (unsigned long long*)(smem + OFF_G1);
    unsigned long long* gb2 = (unsigned long long*)(smem + OFF_G2);
    float* wred = (float*)(smem + OFF_WRED);

    // ---- A fill: input fp32 -> smem bf16 hi, rows of 512B, swizzled ----
#pragma unroll
    for (int it = 0; it < 16; it++) {
        int task = tid + it * 256;          // 4096 tasks
        int m = task >> 5, g = task & 31;   // g = group of 8 dims
        const float* src = input + (size_t)(m0 + m) * D + g * 8;
        float4 f0 = *(const float4*)src;
        float4 f1 = *(const float4*)(src + 4);
        float xs[8] = {f0.x, f0.y, f0.z, f0.w, f1.x, f1.y, f1.z, f1.w};
        uint32_t hw[4];
#pragma unroll
        for (int i = 0; i < 4; i++) {
            __nv_bfloat16 h0 = __float2bfloat16(xs[2 * i]);
            __nv_bfloat16 h1 = __float2bfloat16(xs[2 * i + 1]);
            hw[i] = (uint32_t)__bfloat16_as_ushort(h0) | ((uint32_t)__bfloat16_as_ushort(h1) << 16);
        }
        *(uint4*)(smem + OFF_A + m * 512 + ((g ^ (m & 7)) << 4)) = make_uint4(hw[0], hw[1], hw[2], hw[3]);
    }
    if (tid < TM) { gb1[tid] = 0ull; gb2[tid] = 0ull; c1[tid] = 0ull; c2[tid] = 0ull; }
    __syncthreads();

#pragma unroll 1
    for (int nc = 0; nc < NNC; nc++) {
        float acc[4][4][4];
#pragma unroll
        for (int mi = 0; mi < 4; mi++)
#pragma unroll
            for (int ni = 0; ni < 4; ni++)
#pragma unroll
                for (int c = 0; c < 4; c++) acc[mi][ni][c] = 0.0f;

        uint4 pv[4];
        // preload stage 0: cols [0,64)
        {
#pragma unroll
            for (int i = 0; i < 4; i++) {
                int task = tid + i * 256;
                int n = task >> 3, cc = task & 7;
                pv[i] = *(const uint4*)(g_bhi + (size_t)(nc * NCH + n) * D + cc * 8);
            }
#pragma unroll
            for (int i = 0; i < 4; i++) {
                int task = tid + i * 256;
                int n = task >> 3, cc = task & 7;
                *(uint4*)(smem + OFF_B + n * 128 + ((cc ^ (n & 7)) << 4)) = pv[i];
            }
        }
        __syncthreads();

#pragma unroll 1
        for (int s = 0; s < NST; s++) {
            int buf = s & 1;
            if (s + 1 < NST) {
                int col0 = (s + 1) * 64;
#pragma unroll
                for (int i = 0; i < 4; i++) {
                    int task = tid + i * 256;
                    int n = task >> 3, cc = task & 7;
                    pv[i] = *(const uint4*)(g_bhi + (size_t)(nc * NCH + n) * D + col0 + cc * 8);
                }
            }
            int abase = s * 8;   // A cch base (16B units)
#pragma unroll
            for (int kk = 0; kk < 4; kk++) {
                uint32_t bfr[4][2];
                int ll = lane & 15;
#pragma unroll
                for (int ni = 0; ni < 4; ni++) {
                    int nb = warp_n * 32 + ni * 8 + (ll & 7);
                    int cch = kk * 2 + (ll >> 3);
                    uint32_t baddr = sb + OFF_B + buf * 16384 + nb * 128 + ((cch ^ (nb & 7)) << 4);
                    LDSM_X2(bfr[ni][0], bfr[ni][1], baddr);
                }
#pragma unroll
                for (int mi = 0; mi < 4; mi++) {
                    int row = warp_m * 64 + mi * 16 + (lane & 7) + ((lane >> 3) & 1) * 8;
                    int cch = abase + kk * 2 + (lane >> 4);
                    uint32_t aaddr = sb + OFF_A + row * 512 + ((cch ^ (row & 7)) << 4);
                    uint32_t a0, a1, a2, a3;
                    LDSM_X4(a0, a1, a2, a3, aaddr);
#pragma unroll
                    for (int ni = 0; ni < 4; ni++)
                        MMA16816(acc[mi][ni], a0, a1, a2, a3, bfr[ni][0], bfr[ni][1]);
                }
            }
            if (s + 1 < NST) {
                int nbuf = (s + 1) & 1;
#pragma unroll
                for (int i = 0; i < 4; i++) {
                    int task = tid + i * 256;
                    int n = task >> 3, cc = task & 7;
                    *(uint4*)(smem + OFF_B + nbuf * 16384 + n * 128 + ((cc ^ (n & 7)) << 4)) = pv[i];
                }
            }
            __syncthreads();
        }

        // ---- per-chunk top-2: local -> quad shfl merge -> two-pass atomicMax ----
        unsigned long long pk1[8], pk2[8];
        int idx = 0;
#pragma unroll
        for (int mi = 0; mi < 4; mi++)
#pragma unroll
            for (int h = 0; h < 2; h++) {
                unsigned long long k1 = 0ull, k2 = 0ull;
#pragma unroll
                for (int ni = 0; ni < 4; ni++)
#pragma unroll
                    for (int p = 0; p < 2; p++) {
                        float v = acc[mi][ni][h * 2 + p];
                        unsigned col = (unsigned)(nc * NCH + warp_n * 32 + ni * 8 + (lane & 3) * 2 + p);
                        unsigned long long k = packkey(v, col);
                        if (k > k1) { k2 = k1; k1 = k; }
                        else if (k > k2) k2 = k;
                    }
#pragma unroll
                for (int o = 1; o <= 2; o <<= 1) {
                    unsigned long long o1 = __shfl_xor_sync(0xFFFFFFFFu, k1, o);
                    unsigned long long o2 = __shfl_xor_sync(0xFFFFFFFFu, k2, o);
                    if (o1 > k1) { k2 = (k1 > o2) ? k1 : o2; k1 = o1; }
                    else if (o1 > k2) k2 = o1;
                }
                int r = warp_m * 64 + mi * 16 + h * 8 + (lane >> 2);
                if ((lane & 3) == 0) atomicMax(&c1[r], k1);
                pk1[idx] = k1; pk2[idx] = k2; idx++;
            }
        __syncthreads();
        idx = 0;
#pragma unroll
        for (int mi = 0; mi < 4; mi++)
#pragma unroll
            for (int h = 0; h < 2; h++) {
                if ((lane & 3) == 0) {
                    int r = warp_m * 64 + mi * 16 + h * 8 + (lane >> 2);
                    unsigned long long win = c1[r];
                    unsigned long long loc = (pk1[idx] == win) ? pk2[idx] : pk1[idx];
                    atomicMax(&c2[r], loc);
                }
                idx++;
            }
        __syncthreads();
        if (tid < TM) {
            unsigned long long a = gb1[tid], b = gb2[tid];
            unsigned long long x1 = c1[tid], x2 = c2[tid];
            if (x1 > a) { gb1[tid] = x1; gb2[tid] = (a > x2) ? a : x2; }
            else { gb2[tid] = (b > x1) ? b : x1; }
            c1[tid] = 0ull; c2[tid] = 0ull;
        }
        __syncthreads();
    }

    // ---- flag coarse near-ties for tier-2 fp32 re-scoring ----
    if (tid < TM) {
        float s1 = unpackscore(gb1[tid]);
        float s2 = unpackscore(gb2[tid]);
        if (s1 - s2 < GAP_COARSE) {
            int pos = atomicAdd(&g_cnt, 1);
            if (pos < MAXFLAG) g_list[pos] = m0 + tid;
        }
    }

    // ---- gather epilogue: each warp owns 16 tokens ----
    float dsum = 0.0f;
#pragma unroll 1
    for (int t = 0; t < 16; t++) {
        int m = wid * 16 + t;
        int ind = (int)unpackind(gb1[m]);
        size_t tok = (size_t)(m0 + m);
        const float4* q4 = (const float4*)(g_en + (size_t)ind * D);
        const float4* x4 = (const float4*)(input + tok * D);
        float4* o4 = (float4*)(out + tok * D);
#pragma unroll
        for (int c = 0; c < 2; c++) {
            int dd = c * 32 + lane;
            float4 q = q4[dd];
            float4 x = x4[dd];
            o4[dd] = q;
            float d0 = q.x - x.x, d1 = q.y - x.y, d2 = q.z - x.z, d3 = q.w - x.w;
            dsum += d0 * d0 + d1 * d1 + d2 * d2 + d3 * d3;
        }
        if (lane == 0) indf[tok] = (float)ind;
    }
#pragma unroll
    for (int o = 16; o; o >>= 1) dsum += __shfl_xor_sync(0xFFFFFFFFu, dsum, o);
    if (lane == 0) wred[wid] = dsum;
    __syncthreads();
    if (tid == 0) {
        float s = 0.0f;
        for (int w = 0; w < 8; w++) s += wred[w];
        g_partial[blockIdx.x] = s;
    }
}

// ---------------------------------------------------------------------------
// Kernel 3 (tier 2): exact fp32 re-score of coarse-flagged tokens; 16 tokens
// per CTA-iteration (2x arithmetic intensity per codebook-row load). Extracts
// TOP-4 candidates per token; near-ties (gap < GAP_FINE) go to tier-3.
// ---------------------------------------------------------------------------
__global__ __launch_bounds__(256) void mid_refine_kernel(const float* __restrict__ input,
                                                         float* __restrict__ out,
                                                         float* __restrict__ indf) {
    __shared__ float xT[D][NT];
    __shared__ int stok[NT], sind[NT];
    __shared__ unsigned long long t1[NT], t2[NT], t3[NT], t4[NT];
    int tid = threadIdx.x;
    int cnt = g_cnt;
    if (cnt > MAXFLAG) cnt = MAXFLAG;

    for (int base = blockIdx.x * NT; base < cnt; base += gridDim.x * NT) {
        int nt = cnt - base;
        if (nt > NT) nt = NT;
        if (tid < NT) {
            stok[tid] = g_list[base + ((tid < nt) ? tid : 0)];
            t1[tid] = 0ull; t2[tid] = 0ull; t3[tid] = 0ull; t4[tid] = 0ull;
        }
        __syncthreads();
#pragma unroll
        for (int j = 0; j < NT; j++)
            xT[tid][j] = input[(size_t)stok[j] * D + tid];
        __syncthreads();

        float acc[2][NT];
#pragma unroll
        for (int p = 0; p < 2; p++)
#pragma unroll
            for (int j = 0; j < NT; j++) acc[p][j] = 0.0f;

        const float4* rowA = (const float4*)(g_en + (size_t)tid * D);
        const float4* rowB = (const float4*)(g_en + (size_t)(tid + 256) * D);
#pragma unroll 2
        for (int d4 = 0; d4 < 64; d4++) {
            float4 ra = rowA[d4];
            float4 rb = rowB[d4];
#pragma unroll
            for (int i = 0; i < 4; i++) {
                float va = (&ra.x)[i];
                float vb = (&rb.x)[i];
                const float* xr = &xT[d4 * 4 + i][0];
                float4 x0 = *(const float4*)xr;
                float4 x1 = *(const float4*)(xr + 4);
                float4 x2 = *(const float4*)(xr + 8);
                float4 x3 = *(const float4*)(xr + 12);
                float xv[NT] = {x0.x, x0.y, x0.z, x0.w, x1.x, x1.y, x1.z, x1.w,
                                x2.x, x2.y, x2.z, x2.w, x3.x, x3.y, x3.z, x3.w};
#pragma unroll
                for (int j = 0; j < NT; j++) {
                    acc[0][j] = fmaf(va, xv[j], acc[0][j]);
                    acc[1][j] = fmaf(vb, xv[j], acc[1][j]);
                }
            }
        }
        // 4-pass top-4 extraction (keys recomputed per pass to save registers)
#pragma unroll
        for (int p = 0; p < 2; p++)
#pragma unroll
            for (int j = 0; j < NT; j++)
                atomicMax(&t1[j], packkey(acc[p][j], (unsigned)(tid + p * 256)));
        __syncthreads();
#pragma unroll
        for (int p = 0; p < 2; p++)
#pragma unroll
            for (int j = 0; j < NT; j++) {
                unsigned long long k = packkey(acc[p][j], (unsigned)(tid + p * 256));
                if (k != t1[j]) atomicMax(&t2[j], k);
            }
        __syncthreads();
#pragma unroll
        for (int p = 0; p < 2; p++)
#pragma unroll
            for (int j = 0; j < NT; j++) {
                unsigned long long k = packkey(acc[p][j], (unsigned)(tid + p * 256));
                if (k != t1[j] && k != t2[j]) atomicMax(&t3[j], k);
            }
        __syncthreads();
#pragma unroll
        for (int p = 0; p < 2; p++)
#pragma unroll
            for (int j = 0; j < NT; j++) {
                unsigned long long k = packkey(acc[p][j], (unsigned)(tid + p * 256));
                if (k != t1[j] && k != t2[j] && k != t3[j]) atomicMax(&t4[j], k);
            }
        __syncthreads();
        if (tid < nt) {
            float s1 = unpackscore(t1[tid]);
            float s2 = unpackscore(t2[tid]);
            int i1 = (int)unpackind(t1[tid]);
            int tok = stok[tid];
            sind[tid] = i1;
            indf[tok] = (float)i1;
            if (s1 - s2 < GAP_FINE) {
                int pos = atomicAdd(&g_cnt2, 1);
                if (pos < MAX2) {
                    int i2 = (int)unpackind(t2[tid]);
                    int i3 = (int)unpackind(t3[tid]);
                    int i4 = (int)unpackind(t4[tid]);
                    g_list2[pos] = make_int4(tok, i1 | (i2 << 16), i3 | (i4 << 16), 0);
                }
            }
        }
        __syncthreads();
#pragma unroll 1
        for (int j = 0; j < NT; j++) {
            if (j < nt)
                out[(size_t)stok[j] * D + tid] = g_en[(size_t)sind[j] * D + tid];
        }
        __syncthreads();
    }
}

// ---------------------------------------------------------------------------
// Kernel 4 (tier 3): reference-EMULATING adjudication among top-4 candidates.
// One warp per flagged token; fp64 dots, final dist rounded to fp32
// (reproduces the ~3e-5 quantization grid), argmin with lowest-index tiebreak.
// ---------------------------------------------------------------------------
__global__ __launch_bounds__(256) void refine_kernel(const float* __restrict__ input,
                                                     float* __restrict__ out,
                                                     float* __restrict__ indf) {
    int wid = threadIdx.x >> 5, lane = threadIdx.x & 31;
    int cnt = g_cnt2;
    if (cnt > MAX2) cnt = MAX2;

    for (int li = blockIdx.x * 8 + wid; li < cnt; li += gridDim.x * 8) {
        int4 ent = g_list2[li];
        int tok = ent.x;
        int cand[4] = {ent.y & 0xFFFF, (ent.y >> 16) & 0xFFFF,
                       ent.z & 0xFFFF, (ent.z >> 16) & 0xFFFF};

        const float4* xr = (const float4*)(input + (size_t)tok * D) + lane * 2;
        float4 x0 = xr[0], x1 = xr[1];
        double sx = (double)x0.x * x0.x + (double)x0.y * x0.y + (double)x0.z * x0.z
                  + (double)x0.w * x0.w + (double)x1.x * x1.x + (double)x1.y * x1.y
                  + (double)x1.z * x1.z + (double)x1.w * x1.w;
#pragma unroll
        for (int o = 16; o; o >>= 1) sx += __shfl_xor_sync(0xFFFFFFFFu, sx, o);
        float sx_f = (float)sx;

        unsigned long long bestk = 0xFFFFFFFFFFFFFFFFull;
#pragma unroll
        for (int c = 0; c < 4; c++) {
            int e = cand[c];
            const float4* er = (const float4*)(g_et + (size_t)e * D) + lane * 2;
            float4 e0 = er[0], e1 = er[1];
            double dot = (double)x0.x * e0.x + (double)x0.y * e0.y + (double)x0.z * e0.z
                       + (double)x0.w * e0.w + (double)x1.x * e1.x + (double)x1.y * e1.y
                       + (double)x1.z * e1.z + (double)x1.w * e1.w;
#pragma unroll
            for (int o = 16; o; o >>= 1) dot += __shfl_xor_sync(0xFFFFFFFFu, dot, o);
            float dist_f = (float)((double)sx_f - 2.0 * dot + (double)g_se[e]);
            unsigned long long k =
                ((unsigned long long)__float_as_uint(dist_f) << 32) | (unsigned)e;
            if (k < bestk) bestk = k;
        }
        int ind = (int)(unsigned)bestk;
        if (lane == 0) indf[tok] = (float)ind;
        const float4* q = (const float4*)(g_en + (size_t)ind * D) + lane * 2;
        float4* o4 = (float4*)(out + (size_t)tok * D) + lane * 2;
        o4[0] = q[0];
        o4[1] = q[1];
    }
}

// ---------------------------------------------------------------------------
// Kernel 5a: parallel column partial sums over g_en (4 CTAs x 128 rows).
// ---------------------------------------------------------------------------
__global__ __launch_bounds__(256) void finalize_a_kernel() {
    int col = threadIdx.x, seg = blockIdx.x;
    float s = 0.0f, q = 0.0f;
    const float* base = g_en + (size_t)seg * 128 * D + col;
#pragma unroll 4
    for (int r = 0; r < 128; r++) {
        float v = base[(size_t)r * D];
        s += v;
        q += v * v;
    }
    g_fs[seg][col] = s;
    g_fq[seg][col] = q;
}

// ---------------------------------------------------------------------------
// Kernel 5b: deterministic final combine -> loss.
// entropy = 2*E*sum(en^2) - 2*||sum_i en_i||^2
// ---------------------------------------------------------------------------
__global__ __launch_bounds__(1024) void finalize_b_kernel(float* __restrict__ loss_out) {
    __shared__ double red[1024];
    int tid = threadIdx.x;

    red[tid] = (double)g_partial[tid];
    __syncthreads();
    for (int o = 512; o; o >>= 1) { if (tid < o) red[tid] += red[tid + o]; __syncthreads(); }
    double diff_sum = red[0];
    __syncthreads();

    double vss = 0.0, vq = 0.0;
    if (tid < 256) {
        float S = g_fs[0][tid] + g_fs[1][tid] + g_fs[2][tid] + g_fs[3][tid];
        float Q = g_fq[0][tid] + g_fq[1][tid] + g_fq[2][tid] + g_fq[3][tid];
        vss = (double)S * (double)S;
        vq = (double)Q;
    }
    red[tid] = vss;
    __syncthreads();
    for (int o = 512; o; o >>= 1) { if (tid < o) red[tid] += red[tid + o]; __syncthreads(); }
    double ss2 = red[0];
    __syncthreads();

    red[tid] = vq;
    __syncthreads();
    for (int o = 512; o; o >>= 1) { if (tid < o) red[tid] += red[tid + o]; __syncthreads(); }
    double sumsq = red[0];

    if (tid == 0) {
        double entropy = 2.0 * (double)E * sumsq - 2.0 * ss2;
        double diff = diff_sum / ((double)NTOK * (double)D);
        loss_out[0] = (float)(diff - entropy / (512.0 * 512.0));
    }
}

// ---------------------------------------------------------------------------
extern "C" void kernel_launch(void* const* d_in, const int* in_sizes, int n_in,
                              void* d_out, int out_size) {
    const float* input = (const float*)d_in[0];
    const float* emb = (const float*)d_in[1];
    if (n_in >= 2 && in_sizes[0] == E * D && in_sizes[1] == NTOK * D) {
        input = (const float*)d_in[1];
        emb = (const float*)d_in[0];
    }
    float* out = (float*)d_out;                      // [NTOK*D] quantized output
    float* loss = out + (size_t)NTOK * D;            // [1]      scalar loss
    float* indf = loss + 1;                          // [NTOK]   indices (as float)

    cudaFuncSetAttribute(main_kernel, cudaFuncAttributeMaxDynamicSharedMemorySize,
                         SMEM_TOTAL);

    normalize_kernel<<<E / 8, 256>>>(emb);
    main_kernel<<<GRID_MAIN, 256, SMEM_TOTAL>>>(input, out, indf);
    mid_refine_kernel<<<512, 256>>>(input, out, indf);
    refine_kernel<<<256, 256>>>(input, out, indf);
    finalize_a_kernel<<<4, 256>>>();
    finalize_b_kernel<<<1, 1024>>>(loss);
}